// round 4
// baseline (speedup 1.0000x reference)
#include <cuda_runtime.h>
#include <math.h>

#define BB 8
#define SS 2048
#define HH 1024
#define CC 64
#define NCH 32
#define NN 512      /* BB*CC rows per chunk */
#define II 2048     /* INTER */
#define NROWS 16384 /* BB*SS */

#define TILE 64
#define KT 16
#define SSTR 68

#define EPI_NONE 0
#define EPI_SILU 1
#define EPI_SILU_AUX 2
#define EPI_DSILU 3

// ---------------- device scratch (no allocation allowed) ----------------
__device__ __align__(16) float g_k[NROWS * HH];
__device__ __align__(16) float g_v[NROWS * HH];
__device__ __align__(16) float g_q[NROWS * HH];
__device__ __align__(16) float g_w0[II * HH];
__device__ __align__(16) float g_w1[HH * II];
__device__ __align__(16) float g_w1T[II * HH];
__device__ __align__(16) float g_ln[HH];
__device__ __align__(16) float g_s0[II * HH];
__device__ __align__(16) float g_s1[HH * II];
__device__ __align__(16) float g_sln[HH];
__device__ __align__(16) float g_kc[NN * HH];
__device__ __align__(16) float g_vc[NN * HH];
__device__ __align__(16) float g_z[NN * II];
__device__ __align__(16) float g_h[NN * II];
__device__ __align__(16) float g_dz[NN * II];
__device__ __align__(16) float g_y[NN * HH];
__device__ __align__(16) float g_dy[NN * HH];
__device__ __align__(16) float g_g[NN * HH];
__device__ __align__(16) float g_rs[NN];
__device__ __align__(16) float g_dw0[II * HH];
__device__ __align__(16) float g_dw1[HH * II];
__device__ __align__(16) float g_dln[HH];
__device__ __align__(16) float g_h2[NROWS * II];
__device__ __align__(16) float g_y2[NROWS * HH];
__device__ __align__(16) float g_dotA[BB * NCH];
__device__ __align__(16) float g_dotT[BB * NCH];
__device__ __align__(16) float g_dotE[BB * NCH];
__device__ __align__(16) float g_beta[NCH];
__device__ __align__(16) float g_eta[NCH];
__device__ __align__(16) float g_theta[BB * NCH];
__device__ float g_gnorm;

// ---------------- helpers ----------------
__device__ __forceinline__ float sigm(float x) { return 1.f / (1.f + expf(-x)); }
__device__ __forceinline__ float silu_f(float x) { return x / (1.f + expf(-x)); }
__device__ __forceinline__ float dsilu_f(float x) {
    float s = 1.f / (1.f + expf(-x));
    return s * (1.f + x * (1.f - s));
}

__device__ __forceinline__ float block_sum(float v) {
    __shared__ float sh[32];
    __shared__ float tot;
    int lane = threadIdx.x & 31;
    int w = threadIdx.x >> 5;
#pragma unroll
    for (int o = 16; o > 0; o >>= 1) v += __shfl_xor_sync(0xffffffffu, v, o);
    if (lane == 0) sh[w] = v;
    __syncthreads();
    if (w == 0) {
        float r = (lane < (blockDim.x >> 5)) ? sh[lane] : 0.f;
#pragma unroll
        for (int o = 16; o > 0; o >>= 1) r += __shfl_xor_sync(0xffffffffu, r, o);
        if (lane == 0) tot = r;
    }
    __syncthreads();
    return tot;
}

// ---------------- GEMM NT: C[M,N] = A(M,K) * B(N,K)^T ----------------
__global__ __launch_bounds__(256) void sgemm_nt(
    const float* __restrict__ A, const float* __restrict__ B,
    float* __restrict__ Cmat, float* __restrict__ aux,
    int M, int N, int K, int epi)
{
    __shared__ float As[KT * SSTR];
    __shared__ float Bs[KT * SSTR];
    int t = threadIdx.x;
    int tx = t & 15, ty = t >> 4;
    int bm = blockIdx.y * TILE, bn = blockIdx.x * TILE;
    int lm = t >> 2;
    int lk = (t & 3) << 2;
    const float* Ag = A + (size_t)(bm + lm) * K + lk;
    const float* Bg = B + (size_t)(bn + lm) * K + lk;
    float acc[4][4];
#pragma unroll
    for (int i = 0; i < 4; i++)
#pragma unroll
        for (int j = 0; j < 4; j++) acc[i][j] = 0.f;

    for (int k0 = 0; k0 < K; k0 += KT) {
        float4 a4 = *(const float4*)(Ag + k0);
        float4 b4 = *(const float4*)(Bg + k0);
        __syncthreads();
        As[(lk + 0) * SSTR + lm] = a4.x;
        As[(lk + 1) * SSTR + lm] = a4.y;
        As[(lk + 2) * SSTR + lm] = a4.z;
        As[(lk + 3) * SSTR + lm] = a4.w;
        Bs[(lk + 0) * SSTR + lm] = b4.x;
        Bs[(lk + 1) * SSTR + lm] = b4.y;
        Bs[(lk + 2) * SSTR + lm] = b4.z;
        Bs[(lk + 3) * SSTR + lm] = b4.w;
        __syncthreads();
#pragma unroll
        for (int kk = 0; kk < KT; kk++) {
            float4 av = *(const float4*)(&As[kk * SSTR + ty * 4]);
            float4 bv = *(const float4*)(&Bs[kk * SSTR + tx * 4]);
            acc[0][0] += av.x * bv.x; acc[0][1] += av.x * bv.y; acc[0][2] += av.x * bv.z; acc[0][3] += av.x * bv.w;
            acc[1][0] += av.y * bv.x; acc[1][1] += av.y * bv.y; acc[1][2] += av.y * bv.z; acc[1][3] += av.y * bv.w;
            acc[2][0] += av.z * bv.x; acc[2][1] += av.z * bv.y; acc[2][2] += av.z * bv.z; acc[2][3] += av.z * bv.w;
            acc[3][0] += av.w * bv.x; acc[3][1] += av.w * bv.y; acc[3][2] += av.w * bv.z; acc[3][3] += av.w * bv.w;
        }
    }
#pragma unroll
    for (int i = 0; i < 4; i++) {
        int row = bm + ty * 4 + i;
        size_t off = (size_t)row * N + bn + tx * 4;
        float4 r = make_float4(acc[i][0], acc[i][1], acc[i][2], acc[i][3]);
        if (epi == EPI_SILU) {
            r.x = silu_f(r.x); r.y = silu_f(r.y); r.z = silu_f(r.z); r.w = silu_f(r.w);
        } else if (epi == EPI_SILU_AUX) {
            *(float4*)(aux + off) = r;
            r.x = silu_f(r.x); r.y = silu_f(r.y); r.z = silu_f(r.z); r.w = silu_f(r.w);
        } else if (epi == EPI_DSILU) {
            float4 z4 = *(const float4*)(aux + off);
            r.x *= dsilu_f(z4.x); r.y *= dsilu_f(z4.y); r.z *= dsilu_f(z4.z); r.w *= dsilu_f(z4.w);
        }
        *(float4*)(Cmat + off) = r;
    }
}

// ---------------- GEMM TN: C[M,N] = A(K,M)^T-view * B(K,N) ----------------
// A row-major (K rows, width M); B row-major (K rows, width N)
__global__ __launch_bounds__(256) void sgemm_tn(
    const float* __restrict__ A, const float* __restrict__ B,
    float* __restrict__ Cmat, int M, int N, int K)
{
    __shared__ float As[KT * SSTR];
    __shared__ float Bs[KT * SSTR];
    int t = threadIdx.x;
    int tx = t & 15, ty = t >> 4;
    int bm = blockIdx.y * TILE, bn = blockIdx.x * TILE;
    int lk = t >> 4;
    int lc = (t & 15) << 2;
    float acc[4][4];
#pragma unroll
    for (int i = 0; i < 4; i++)
#pragma unroll
        for (int j = 0; j < 4; j++) acc[i][j] = 0.f;

    for (int k0 = 0; k0 < K; k0 += KT) {
        float4 a4 = *(const float4*)(A + (size_t)(k0 + lk) * M + bm + lc);
        float4 b4 = *(const float4*)(B + (size_t)(k0 + lk) * N + bn + lc);
        __syncthreads();
        *(float4*)(&As[lk * SSTR + lc]) = a4;
        *(float4*)(&Bs[lk * SSTR + lc]) = b4;
        __syncthreads();
#pragma unroll
        for (int kk = 0; kk < KT; kk++) {
            float4 av = *(const float4*)(&As[kk * SSTR + ty * 4]);
            float4 bv = *(const float4*)(&Bs[kk * SSTR + tx * 4]);
            acc[0][0] += av.x * bv.x; acc[0][1] += av.x * bv.y; acc[0][2] += av.x * bv.z; acc[0][3] += av.x * bv.w;
            acc[1][0] += av.y * bv.x; acc[1][1] += av.y * bv.y; acc[1][2] += av.y * bv.z; acc[1][3] += av.y * bv.w;
            acc[2][0] += av.z * bv.x; acc[2][1] += av.z * bv.y; acc[2][2] += av.z * bv.z; acc[2][3] += av.z * bv.w;
            acc[3][0] += av.w * bv.x; acc[3][1] += av.w * bv.y; acc[3][2] += av.w * bv.z; acc[3][3] += av.w * bv.w;
        }
    }
#pragma unroll
    for (int i = 0; i < 4; i++) {
        int row = bm + ty * 4 + i;
        size_t off = (size_t)row * N + bn + tx * 4;
        float4 r = make_float4(acc[i][0], acc[i][1], acc[i][2], acc[i][3]);
        *(float4*)(Cmat + off) = r;
    }
}

// ---------------- elementwise / reduction kernels ----------------
__global__ __launch_bounds__(256) void init_mem(
    const float* __restrict__ w0, const float* __restrict__ w1, const float* __restrict__ ln)
{
    int n = II * HH;
    for (int i = blockIdx.x * blockDim.x + threadIdx.x; i < n; i += gridDim.x * blockDim.x) {
        g_w0[i] = w0[i]; g_s0[i] = 0.f;
        g_w1[i] = w1[i]; g_s1[i] = 0.f;
        if (i < HH) { g_ln[i] = ln[i]; g_sln[i] = 0.f; }
    }
}

__global__ void transpose_w1() {
    __shared__ float tile[32][33];
    int j0 = blockIdx.x * 32;  // II dim
    int i0 = blockIdx.y * 32;  // HH dim
    int tx = threadIdx.x, ty = threadIdx.y;  // 32 x 8
#pragma unroll
    for (int k = 0; k < 32; k += 8)
        tile[ty + k][tx] = g_w1[(size_t)(i0 + ty + k) * II + j0 + tx];
    __syncthreads();
#pragma unroll
    for (int k = 0; k < 32; k += 8)
        g_w1T[(size_t)(j0 + ty + k) * HH + i0 + tx] = tile[tx][ty + k];
}

__global__ __launch_bounds__(256) void rmsnorm_rows(float* __restrict__ buf, const float* __restrict__ w) {
    int r = blockIdx.x;
    int t = threadIdx.x;
    float4* row = (float4*)(buf + (size_t)r * HH);
    float4 v = row[t];
    float ss = v.x * v.x + v.y * v.y + v.z * v.z + v.w * v.w;
    ss = block_sum(ss);
    float rs = rsqrtf(ss / HH + 1e-6f);
    float4 wv = ((const float4*)w)[t];
    v.x *= rs * wv.x; v.y *= rs * wv.y; v.z *= rs * wv.z; v.w *= rs * wv.w;
    row[t] = v;
}

__global__ __launch_bounds__(256) void coeff_dot(
    const float* __restrict__ x, const float* __restrict__ aw,
    const float* __restrict__ tw, const float* __restrict__ ew)
{
    int bc = blockIdx.x;
    int b = bc >> 5, nc = bc & 31;
    const float4* xf = (const float4*)(x + (size_t)(b * SS + nc * CC) * HH);
    const float4* a4 = (const float4*)aw;
    const float4* t4 = (const float4*)tw;
    const float4* e4 = (const float4*)ew;
    const int L4 = CC * HH / 4;
    float sa = 0.f, st = 0.f, se = 0.f;
    for (int i = threadIdx.x; i < L4; i += blockDim.x) {
        float4 xv = xf[i];
        float4 av = a4[i]; sa += xv.x * av.x + xv.y * av.y + xv.z * av.z + xv.w * av.w;
        float4 tv = t4[i]; st += xv.x * tv.x + xv.y * tv.y + xv.z * tv.z + xv.w * tv.w;
        float4 ev = e4[i]; se += xv.x * ev.x + xv.y * ev.y + xv.z * ev.z + xv.w * ev.w;
    }
    sa = block_sum(sa);
    st = block_sum(st);
    se = block_sum(se);
    if (threadIdx.x == 0) { g_dotA[bc] = sa; g_dotT[bc] = st; g_dotE[bc] = se; }
}

__global__ void coeff_finalize() {
    int t = threadIdx.x;
    if (t < BB * NCH) g_theta[t] = sigm(g_dotT[t]) * 0.01f;
    if (t < NCH) {
        float sa = 0.f, se = 0.f;
        for (int b = 0; b < BB; b++) { sa += g_dotA[b * NCH + t]; se += g_dotE[b * NCH + t]; }
        float al = sigm(sa / (float)BB);
        g_beta[t] = 1.f - al;
        g_eta[t] = sigm(se / (float)BB);
    }
}

__global__ __launch_bounds__(256) void gather_chunk(int c) {
    const int H4 = HH / 4;
    int n4 = NN * H4;
    for (int i = blockIdx.x * blockDim.x + threadIdx.x; i < n4; i += gridDim.x * blockDim.x) {
        int m = i / H4, cq = i - m * H4;
        int src = ((m >> 6) * SS + c * CC + (m & 63)) * H4 + cq;
        ((float4*)g_kc)[i] = ((const float4*)g_k)[src];
        ((float4*)g_vc)[i] = ((const float4*)g_v)[src];
    }
}

// backward through rmsnorm + residual + weighted MSE
__global__ __launch_bounds__(256) void chunk_bwd_y(int c) {
    int r = blockIdx.x;
    int t = threadIdx.x;
    int b = r >> 6;
    float4 y4 = ((const float4*)(g_y + (size_t)r * HH))[t];
    float ss = y4.x * y4.x + y4.y * y4.y + y4.z * y4.z + y4.w * y4.w;
    ss = block_sum(ss);
    float rs = rsqrtf(ss / HH + 1e-6f);
    float th = g_theta[b * NCH + c];
    float scale = 2.f * th / ((float)NN * (float)HH);
    float4 k4 = ((const float4*)(g_kc + (size_t)r * HH))[t];
    float4 v4 = ((const float4*)(g_vc + (size_t)r * HH))[t];
    float4 l4 = ((const float4*)g_ln)[t];
    float4 gg;
    gg.x = scale * (k4.x + y4.x * rs * l4.x - v4.x);
    gg.y = scale * (k4.y + y4.y * rs * l4.y - v4.y);
    gg.z = scale * (k4.z + y4.z * rs * l4.z - v4.z);
    gg.w = scale * (k4.w + y4.w * rs * l4.w - v4.w);
    float sv = gg.x * l4.x * y4.x + gg.y * l4.y * y4.y + gg.z * l4.z * y4.z + gg.w * l4.w * y4.w;
    sv = block_sum(sv);
    float c3 = rs * rs * rs * sv / (float)HH;
    float4 dy;
    dy.x = rs * gg.x * l4.x - c3 * y4.x;
    dy.y = rs * gg.y * l4.y - c3 * y4.y;
    dy.z = rs * gg.z * l4.z - c3 * y4.z;
    dy.w = rs * gg.w * l4.w - c3 * y4.w;
    ((float4*)(g_g + (size_t)r * HH))[t] = gg;
    ((float4*)(g_dy + (size_t)r * HH))[t] = dy;
    if (t == 0) {
        g_rs[r] = rs;
        if (r == 0) g_gnorm = 0.f;
    }
}

__global__ __launch_bounds__(256) void dln_reduce() {
    int col = blockIdx.x * blockDim.x + threadIdx.x;
    float s = 0.f;
    for (int r = 0; r < NN; r++)
        s += g_g[(size_t)r * HH + col] * g_y[(size_t)r * HH + col] * g_rs[r];
    g_dln[col] = s;
}

__global__ __launch_bounds__(256) void grad_sumsq() {
    const int n0 = II * HH, n1 = 2 * II * HH, nt = 2 * II * HH + HH;
    float s = 0.f;
    for (int i = blockIdx.x * blockDim.x + threadIdx.x; i < nt; i += gridDim.x * blockDim.x) {
        float gv = (i < n0) ? g_dw0[i] : (i < n1 ? g_dw1[i - n0] : g_dln[i - n1]);
        s += gv * gv;
    }
    s = block_sum(s);
    if (threadIdx.x == 0) atomicAdd(&g_gnorm, s);
}

__global__ __launch_bounds__(256) void update_params(int c) {
    float total = sqrtf(g_gnorm);
    float clip = fminf(1.0f / (total + 1e-6f), 1.0f);
    float eta = g_eta[c], beta = g_beta[c];
    const int n0 = II * HH, n1 = 2 * II * HH, nt = 2 * II * HH + HH;
    for (int i = blockIdx.x * blockDim.x + threadIdx.x; i < nt; i += gridDim.x * blockDim.x) {
        float *p, *sp;
        float gv;
        int j;
        if (i < n0) { j = i; p = g_w0; sp = g_s0; gv = g_dw0[j]; }
        else if (i < n1) { j = i - n0; p = g_w1; sp = g_s1; gv = g_dw1[j]; }
        else { j = i - n1; p = g_ln; sp = g_sln; gv = g_dln[j]; }
        float ns = eta * sp[j] - gv * clip;
        sp[j] = ns;
        p[j] = beta * p[j] + ns;
    }
}

__global__ __launch_bounds__(256) void final_out(float* __restrict__ out) {
    int r = blockIdx.x, t = threadIdx.x;
    float4 y4 = ((const float4*)(g_y2 + (size_t)r * HH))[t];
    float ss = y4.x * y4.x + y4.y * y4.y + y4.z * y4.z + y4.w * y4.w;
    ss = block_sum(ss);
    float rs = rsqrtf(ss / HH + 1e-6f);
    float4 q4 = ((const float4*)(g_q + (size_t)r * HH))[t];
    float4 l4 = ((const float4*)g_ln)[t];
    float4 o;
    o.x = q4.x + y4.x * rs * l4.x;
    o.y = q4.y + y4.y * rs * l4.y;
    o.z = q4.z + y4.z * rs * l4.z;
    o.w = q4.w + y4.w * rs * l4.w;
    ((float4*)(out + (size_t)r * HH))[t] = o;
}

// ---------------- host launcher ----------------
extern "C" void kernel_launch(void* const* d_in, const int* in_sizes, int n_in,
                              void* d_out, int out_size) {
    const float* x   = (const float*)d_in[0];
    const float* wq  = (const float*)d_in[1];
    const float* wk  = (const float*)d_in[2];
    const float* wv  = (const float*)d_in[3];
    const float* qn  = (const float*)d_in[4];
    const float* kn  = (const float*)d_in[5];
    const float* aw  = (const float*)d_in[6];
    const float* tw  = (const float*)d_in[7];
    const float* ew  = (const float*)d_in[8];
    const float* mw0 = (const float*)d_in[9];
    const float* mw1 = (const float*)d_in[10];
    const float* mln = (const float*)d_in[11];
    float* out = (float*)d_out;

    float *k_, *v_, *q_, *w0_, *w1_, *w1T_, *kc_, *z_, *h_, *dz_, *y_, *dy_, *dw0_, *dw1_, *h2_, *y2_;
    cudaGetSymbolAddress((void**)&k_,   g_k);
    cudaGetSymbolAddress((void**)&v_,   g_v);
    cudaGetSymbolAddress((void**)&q_,   g_q);
    cudaGetSymbolAddress((void**)&w0_,  g_w0);
    cudaGetSymbolAddress((void**)&w1_,  g_w1);
    cudaGetSymbolAddress((void**)&w1T_, g_w1T);
    cudaGetSymbolAddress((void**)&kc_,  g_kc);
    cudaGetSymbolAddress((void**)&z_,   g_z);
    cudaGetSymbolAddress((void**)&h_,   g_h);
    cudaGetSymbolAddress((void**)&dz_,  g_dz);
    cudaGetSymbolAddress((void**)&y_,   g_y);
    cudaGetSymbolAddress((void**)&dy_,  g_dy);
    cudaGetSymbolAddress((void**)&dw0_, g_dw0);
    cudaGetSymbolAddress((void**)&dw1_, g_dw1);
    cudaGetSymbolAddress((void**)&h2_,  g_h2);
    cudaGetSymbolAddress((void**)&y2_,  g_y2);

    // ---- init memory params + surprise state ----
    init_mem<<<1024, 256>>>(mw0, mw1, mln);
    transpose_w1<<<dim3(II / 32, HH / 32), dim3(32, 8)>>>();

    // ---- precompute k, v, q ----
    dim3 gKVQ(HH / TILE, NROWS / TILE);
    sgemm_nt<<<gKVQ, 256>>>(x, wk, k_, nullptr, NROWS, HH, HH, EPI_SILU);
    rmsnorm_rows<<<NROWS, 256>>>(k_, kn);
    sgemm_nt<<<gKVQ, 256>>>(x, wv, v_, nullptr, NROWS, HH, HH, EPI_SILU);
    sgemm_nt<<<gKVQ, 256>>>(x, wq, q_, nullptr, NROWS, HH, HH, EPI_SILU);
    rmsnorm_rows<<<NROWS, 256>>>(q_, qn);

    // ---- adaptive coefficients ----
    coeff_dot<<<BB * NCH, 256>>>(x, aw, tw, ew);
    coeff_finalize<<<1, 256>>>();

    // ---- sequential scan over chunks ----
    for (int c = 0; c < NCH; c++) {
        gather_chunk<<<256, 256>>>(c);
        // z = kc @ w0^T ; h = silu(z)
        sgemm_nt<<<dim3(II / TILE, NN / TILE), 256>>>(kc_, w0_, h_, z_, NN, II, HH, EPI_SILU_AUX);
        // y = h @ w1^T
        sgemm_nt<<<dim3(HH / TILE, NN / TILE), 256>>>(h_, w1_, y_, nullptr, NN, HH, II, EPI_NONE);
        // backward through residual + rmsnorm + MSE
        chunk_bwd_y<<<NN, 256>>>(c);
        dln_reduce<<<HH / 256, 256>>>();
        // d_z = (d_y @ w1) * silu'(z)  (NT via w1T)
        sgemm_nt<<<dim3(II / TILE, NN / TILE), 256>>>(dy_, w1T_, dz_, z_, NN, II, HH, EPI_DSILU);
        // d_w1 = d_y^T @ h   (HH x II)
        sgemm_tn<<<dim3(II / TILE, HH / TILE), 256>>>(dy_, h_, dw1_, HH, II, NN);
        // d_w0 = d_z^T @ kc  (II x HH)
        sgemm_tn<<<dim3(HH / TILE, II / TILE), 256>>>(dz_, kc_, dw0_, II, HH, NN);
        // grad norm + clipped EMA update
        grad_sumsq<<<512, 256>>>();
        update_params<<<1024, 256>>>(c);
        transpose_w1<<<dim3(II / 32, HH / 32), dim3(32, 8)>>>();
    }

    // ---- retrieval with final memory ----
    sgemm_nt<<<dim3(II / TILE, NROWS / TILE), 256>>>(q_, w0_, h2_, nullptr, NROWS, II, HH, EPI_SILU);
    sgemm_nt<<<dim3(HH / TILE, NROWS / TILE), 256>>>(h2_, w1_, y2_, nullptr, NROWS, HH, II, EPI_NONE);
    final_out<<<NROWS, 256>>>(out);
}

// round 5
// speedup vs baseline: 2.0286x; 2.0286x over previous
#include <cuda_runtime.h>
#include <math.h>
#include <stdint.h>

#define BB 8
#define SS 2048
#define HH 1024
#define CC 64
#define NCH 32
#define NN 512      /* BB*CC rows per chunk */
#define II 2048     /* INTER */
#define NROWS 16384 /* BB*SS */

#define EPI_NONE 0
#define EPI_SILU 1
#define EPI_SILU_AUX 2
#define EPI_DSILU 3
#define EPI_GRAD 4

// ---------------- device scratch (no allocation allowed) ----------------
__device__ __align__(16) float g_k[NROWS * HH];
__device__ __align__(16) float g_v[NROWS * HH];
__device__ __align__(16) float g_q[NROWS * HH];
__device__ __align__(16) float g_w0[II * HH];
__device__ __align__(16) float g_w1[HH * II];
__device__ __align__(16) float g_ln[HH];
__device__ __align__(16) float g_s0[II * HH];
__device__ __align__(16) float g_s1[HH * II];
__device__ __align__(16) float g_sln[HH];
__device__ __align__(16) float g_kc[NN * HH];
__device__ __align__(16) float g_vc[NN * HH];
__device__ __align__(16) float g_z[NN * II];
__device__ __align__(16) float g_h[NN * II];
__device__ __align__(16) float g_dz[NN * II];
__device__ __align__(16) float g_y[NN * HH];
__device__ __align__(16) float g_dy[NN * HH];
__device__ __align__(16) float g_g[NN * HH];   // holds g*y*rs (for dln)
__device__ __align__(16) float g_dw0[II * HH];
__device__ __align__(16) float g_dw1[HH * II];
__device__ __align__(16) float g_dln[HH];
__device__ __align__(16) float g_h2[NROWS * II];
__device__ __align__(16) float g_y2[NROWS * HH];
__device__ __align__(16) float g_dotA[BB * NCH];
__device__ __align__(16) float g_dotT[BB * NCH];
__device__ __align__(16) float g_dotE[BB * NCH];
__device__ __align__(16) float g_beta[NCH];
__device__ __align__(16) float g_eta[NCH];
__device__ __align__(16) float g_theta[BB * NCH];
__device__ float g_gnorm;

// ---------------- helpers ----------------
__device__ __forceinline__ float sigm(float x) { return 1.f / (1.f + expf(-x)); }
__device__ __forceinline__ float silu_f(float x) { return x / (1.f + expf(-x)); }
__device__ __forceinline__ float dsilu_f(float x) {
    float s = 1.f / (1.f + expf(-x));
    return s * (1.f + x * (1.f - s));
}

__device__ __forceinline__ uint32_t f2tf(float x) {
    uint32_t r;
    asm("cvt.rna.tf32.f32 %0, %1;" : "=r"(r) : "f"(x));
    return r;
}

__device__ __forceinline__ void mma8(float* d, const uint32_t* a, const uint32_t* b) {
    asm volatile(
        "mma.sync.aligned.m16n8k8.row.col.f32.tf32.tf32.f32 "
        "{%0,%1,%2,%3}, {%4,%5,%6,%7}, {%8,%9}, {%0,%1,%2,%3};"
        : "+f"(d[0]), "+f"(d[1]), "+f"(d[2]), "+f"(d[3])
        : "r"(a[0]), "r"(a[1]), "r"(a[2]), "r"(a[3]), "r"(b[0]), "r"(b[1]));
}

__device__ __forceinline__ float block_sum(float v) {
    __shared__ float sh[32];
    __shared__ float tot;
    int lane = threadIdx.x & 31;
    int w = threadIdx.x >> 5;
#pragma unroll
    for (int o = 16; o > 0; o >>= 1) v += __shfl_xor_sync(0xffffffffu, v, o);
    if (lane == 0) sh[w] = v;
    __syncthreads();
    if (w == 0) {
        float r = (lane < (blockDim.x >> 5)) ? sh[lane] : 0.f;
#pragma unroll
        for (int o = 16; o > 0; o >>= 1) r += __shfl_xor_sync(0xffffffffu, r, o);
        if (lane == 0) tot = r;
    }
    __syncthreads();
    return tot;
}

// ---------------- tf32 tensor-core GEMM ----------------
// C[M,N] = opA(A) * opB(B)
//   AT=true : A is M x K row-major (NT / NN style)     -> transpose-stage
//   AT=false: A is K x M row-major (TN style, = A^T)   -> direct-stage
//   BT=true : B is N x K row-major (NT style, = B^T)   -> transpose-stage
//   BT=false: B is K x N row-major (NN / TN style)     -> direct-stage
// Requires: M%BM==0, N%BN==0, K%32==0.
template<int BM, int BN, int WM, int WN, int NWARP, bool AT, bool BT>
__global__ __launch_bounds__(NWARP * 32) void gemm_tf32(
    const float* __restrict__ A, const float* __restrict__ B,
    float* __restrict__ C, float* __restrict__ aux,
    int M, int N, int K, int epi)
{
    constexpr int NT = NWARP * 32;
    constexpr int BK = 32;
    constexpr int SA = BM + 8;
    constexpr int SB = BN + 8;
    __shared__ uint32_t As[BK * SA];
    __shared__ uint32_t Bs[BK * SB];

    const int t = threadIdx.x;
    const int bm = blockIdx.y * BM, bn = blockIdx.x * BN;
    const int wid = t >> 5, lane = t & 31;
    const int wm = (wid % (BM / WM)) * WM;
    const int wn = (wid / (BM / WM)) * WN;
    constexpr int MI = WM / 16, NI = WN / 8;
    const int gp = lane >> 2, kq = lane & 3;

    float acc[MI][NI][4];
#pragma unroll
    for (int i = 0; i < MI; i++)
#pragma unroll
        for (int j = 0; j < NI; j++)
#pragma unroll
            for (int q = 0; q < 4; q++) acc[i][j][q] = 0.f;

    float4 ar[4], br[4];

    auto loadA = [&](int k0) {
#pragma unroll
        for (int p = 0; p < 4; p++) {
            if constexpr (AT) {
                int m = p * (NT / 8) + (t >> 3);
                int kk = (t & 7) * 4;
                ar[p] = *(const float4*)(A + (size_t)(bm + m) * K + k0 + kk);
            } else {
                constexpr int CH = BM / 4;
                int kk = p * (NT / CH) + t / CH;
                int m4 = (t % CH) * 4;
                ar[p] = *(const float4*)(A + (size_t)(k0 + kk) * M + bm + m4);
            }
        }
    };
    auto loadB = [&](int k0) {
#pragma unroll
        for (int p = 0; p < 4; p++) {
            if constexpr (BT) {
                int n = p * (NT / 8) + (t >> 3);
                int kk = (t & 7) * 4;
                br[p] = *(const float4*)(B + (size_t)(bn + n) * K + k0 + kk);
            } else {
                constexpr int CH = BN / 4;
                int kk = p * (NT / CH) + t / CH;
                int n4 = (t % CH) * 4;
                br[p] = *(const float4*)(B + (size_t)(k0 + kk) * N + bn + n4);
            }
        }
    };
    auto storeAB = [&]() {
#pragma unroll
        for (int p = 0; p < 4; p++) {
            if constexpr (AT) {
                int m = p * (NT / 8) + (t >> 3);
                int kk = (t & 7) * 4;
                As[(kk + 0) * SA + m] = f2tf(ar[p].x);
                As[(kk + 1) * SA + m] = f2tf(ar[p].y);
                As[(kk + 2) * SA + m] = f2tf(ar[p].z);
                As[(kk + 3) * SA + m] = f2tf(ar[p].w);
            } else {
                constexpr int CH = BM / 4;
                int kk = p * (NT / CH) + t / CH;
                int m4 = (t % CH) * 4;
                uint32_t* d = &As[kk * SA + m4];
                d[0] = f2tf(ar[p].x); d[1] = f2tf(ar[p].y);
                d[2] = f2tf(ar[p].z); d[3] = f2tf(ar[p].w);
            }
        }
#pragma unroll
        for (int p = 0; p < 4; p++) {
            if constexpr (BT) {
                int n = p * (NT / 8) + (t >> 3);
                int kk = (t & 7) * 4;
                Bs[(kk + 0) * SB + n] = f2tf(br[p].x);
                Bs[(kk + 1) * SB + n] = f2tf(br[p].y);
                Bs[(kk + 2) * SB + n] = f2tf(br[p].z);
                Bs[(kk + 3) * SB + n] = f2tf(br[p].w);
            } else {
                constexpr int CH = BN / 4;
                int kk = p * (NT / CH) + t / CH;
                int n4 = (t % CH) * 4;
                uint32_t* d = &Bs[kk * SB + n4];
                d[0] = f2tf(br[p].x); d[1] = f2tf(br[p].y);
                d[2] = f2tf(br[p].z); d[3] = f2tf(br[p].w);
            }
        }
    };

    loadA(0);
    loadB(0);
    for (int k0 = 0; k0 < K; k0 += BK) {
        __syncthreads();
        storeAB();
        __syncthreads();
        if (k0 + BK < K) { loadA(k0 + BK); loadB(k0 + BK); }
#pragma unroll
        for (int ks = 0; ks < 4; ks++) {
            uint32_t af[MI][4], bf[NI][2];
#pragma unroll
            for (int mi = 0; mi < MI; mi++) {
                int r0 = wm + mi * 16 + gp;
                af[mi][0] = As[(ks * 8 + kq) * SA + r0];
                af[mi][1] = As[(ks * 8 + kq) * SA + r0 + 8];
                af[mi][2] = As[(ks * 8 + kq + 4) * SA + r0];
                af[mi][3] = As[(ks * 8 + kq + 4) * SA + r0 + 8];
            }
#pragma unroll
            for (int ni = 0; ni < NI; ni++) {
                int c0 = wn + ni * 8 + gp;
                bf[ni][0] = Bs[(ks * 8 + kq) * SB + c0];
                bf[ni][1] = Bs[(ks * 8 + kq + 4) * SB + c0];
            }
#pragma unroll
            for (int mi = 0; mi < MI; mi++)
#pragma unroll
                for (int ni = 0; ni < NI; ni++)
                    mma8(acc[mi][ni], af[mi], bf[ni]);
        }
    }

    // epilogue
    float gs = 0.f;
#pragma unroll
    for (int mi = 0; mi < MI; mi++) {
#pragma unroll
        for (int ni = 0; ni < NI; ni++) {
            int r0 = bm + wm + mi * 16 + gp;
            int c = bn + wn + ni * 8 + kq * 2;
            size_t o0 = (size_t)r0 * N + c;
            size_t o1 = (size_t)(r0 + 8) * N + c;
            float2 v0 = make_float2(acc[mi][ni][0], acc[mi][ni][1]);
            float2 v1 = make_float2(acc[mi][ni][2], acc[mi][ni][3]);
            if (epi == EPI_SILU) {
                v0.x = silu_f(v0.x); v0.y = silu_f(v0.y);
                v1.x = silu_f(v1.x); v1.y = silu_f(v1.y);
            } else if (epi == EPI_SILU_AUX) {
                *(float2*)(aux + o0) = v0;
                *(float2*)(aux + o1) = v1;
                v0.x = silu_f(v0.x); v0.y = silu_f(v0.y);
                v1.x = silu_f(v1.x); v1.y = silu_f(v1.y);
            } else if (epi == EPI_DSILU) {
                float2 z0 = *(const float2*)(aux + o0);
                float2 z1 = *(const float2*)(aux + o1);
                v0.x *= dsilu_f(z0.x); v0.y *= dsilu_f(z0.y);
                v1.x *= dsilu_f(z1.x); v1.y *= dsilu_f(z1.y);
            } else if (epi == EPI_GRAD) {
                gs += v0.x * v0.x + v0.y * v0.y + v1.x * v1.x + v1.y * v1.y;
            }
            *(float2*)(C + o0) = v0;
            *(float2*)(C + o1) = v1;
        }
    }
    if (epi == EPI_GRAD) {
        gs = block_sum(gs);
        if (t == 0) atomicAdd(&g_gnorm, gs);
    }
}

// ---------------- elementwise / reduction kernels ----------------
__global__ __launch_bounds__(256) void init_mem(
    const float* __restrict__ w0, const float* __restrict__ w1, const float* __restrict__ ln)
{
    int n = II * HH;
    for (int i = blockIdx.x * blockDim.x + threadIdx.x; i < n; i += gridDim.x * blockDim.x) {
        g_w0[i] = w0[i]; g_s0[i] = 0.f;
        g_w1[i] = w1[i]; g_s1[i] = 0.f;
        if (i < HH) { g_ln[i] = ln[i]; g_sln[i] = 0.f; }
    }
}

__global__ __launch_bounds__(256) void rmsnorm_rows(float* __restrict__ buf, const float* __restrict__ w) {
    int r = blockIdx.x;
    int t = threadIdx.x;
    float4* row = (float4*)(buf + (size_t)r * HH);
    float4 v = row[t];
    float ss = v.x * v.x + v.y * v.y + v.z * v.z + v.w * v.w;
    ss = block_sum(ss);
    float rs = rsqrtf(ss / HH + 1e-6f);
    float4 wv = ((const float4*)w)[t];
    v.x *= rs * wv.x; v.y *= rs * wv.y; v.z *= rs * wv.z; v.w *= rs * wv.w;
    row[t] = v;
}

__global__ __launch_bounds__(256) void coeff_dot(
    const float* __restrict__ x, const float* __restrict__ aw,
    const float* __restrict__ tw, const float* __restrict__ ew)
{
    int bc = blockIdx.x;
    int b = bc >> 5, nc = bc & 31;
    const float4* xf = (const float4*)(x + (size_t)(b * SS + nc * CC) * HH);
    const float4* a4 = (const float4*)aw;
    const float4* t4 = (const float4*)tw;
    const float4* e4 = (const float4*)ew;
    const int L4 = CC * HH / 4;
    float sa = 0.f, st = 0.f, se = 0.f;
    for (int i = threadIdx.x; i < L4; i += blockDim.x) {
        float4 xv = xf[i];
        float4 av = a4[i]; sa += xv.x * av.x + xv.y * av.y + xv.z * av.z + xv.w * av.w;
        float4 tv = t4[i]; st += xv.x * tv.x + xv.y * tv.y + xv.z * tv.z + xv.w * tv.w;
        float4 ev = e4[i]; se += xv.x * ev.x + xv.y * ev.y + xv.z * ev.z + xv.w * ev.w;
    }
    sa = block_sum(sa);
    st = block_sum(st);
    se = block_sum(se);
    if (threadIdx.x == 0) { g_dotA[bc] = sa; g_dotT[bc] = st; g_dotE[bc] = se; }
}

__global__ void coeff_finalize() {
    int t = threadIdx.x;
    if (t < BB * NCH) g_theta[t] = sigm(g_dotT[t]) * 0.01f;
    if (t < NCH) {
        float sa = 0.f, se = 0.f;
        for (int b = 0; b < BB; b++) { sa += g_dotA[b * NCH + t]; se += g_dotE[b * NCH + t]; }
        float al = sigm(sa / (float)BB);
        g_beta[t] = 1.f - al;
        g_eta[t] = sigm(se / (float)BB);
    }
}

__global__ __launch_bounds__(256) void gather_chunk(int c) {
    const int H4 = HH / 4;
    int n4 = NN * H4;
    for (int i = blockIdx.x * blockDim.x + threadIdx.x; i < n4; i += gridDim.x * blockDim.x) {
        int m = i / H4, cq = i - m * H4;
        int src = ((m >> 6) * SS + c * CC + (m & 63)) * H4 + cq;
        ((float4*)g_kc)[i] = ((const float4*)g_k)[src];
        ((float4*)g_vc)[i] = ((const float4*)g_v)[src];
    }
}

// backward through rmsnorm + residual + weighted MSE; stores g*y*rs for dln
__global__ __launch_bounds__(256) void chunk_bwd_y(int c) {
    int r = blockIdx.x;
    int t = threadIdx.x;
    int b = r >> 6;
    float4 y4 = ((const float4*)(g_y + (size_t)r * HH))[t];
    float ss = y4.x * y4.x + y4.y * y4.y + y4.z * y4.z + y4.w * y4.w;
    ss = block_sum(ss);
    float rs = rsqrtf(ss / HH + 1e-6f);
    float th = g_theta[b * NCH + c];
    float scale = 2.f * th / ((float)NN * (float)HH);
    float4 k4 = ((const float4*)(g_kc + (size_t)r * HH))[t];
    float4 v4 = ((const float4*)(g_vc + (size_t)r * HH))[t];
    float4 l4 = ((const float4*)g_ln)[t];
    float4 gg;
    gg.x = scale * (k4.x + y4.x * rs * l4.x - v4.x);
    gg.y = scale * (k4.y + y4.y * rs * l4.y - v4.y);
    gg.z = scale * (k4.z + y4.z * rs * l4.z - v4.z);
    gg.w = scale * (k4.w + y4.w * rs * l4.w - v4.w);
    float sv = gg.x * l4.x * y4.x + gg.y * l4.y * y4.y + gg.z * l4.z * y4.z + gg.w * l4.w * y4.w;
    sv = block_sum(sv);
    float c3 = rs * rs * rs * sv / (float)HH;
    float4 dy;
    dy.x = rs * gg.x * l4.x - c3 * y4.x;
    dy.y = rs * gg.y * l4.y - c3 * y4.y;
    dy.z = rs * gg.z * l4.z - c3 * y4.z;
    dy.w = rs * gg.w * l4.w - c3 * y4.w;
    // product for dln reduction: g * (y * rs)
    float4 pr;
    pr.x = gg.x * y4.x * rs;
    pr.y = gg.y * y4.y * rs;
    pr.z = gg.z * y4.z * rs;
    pr.w = gg.w * y4.w * rs;
    ((float4*)(g_g + (size_t)r * HH))[t] = pr;
    ((float4*)(g_dy + (size_t)r * HH))[t] = dy;
    if (r == 0) {
        if (t == 0) g_gnorm = 0.f;
        for (int i = t; i < HH; i += 256) g_dln[i] = 0.f;
    }
}

__global__ __launch_bounds__(256) void dln_partial() {
    int col = blockIdx.x * 256 + threadIdx.x;
    int r0 = blockIdx.y * (NN / 8);
    float s = 0.f;
#pragma unroll 8
    for (int r = r0; r < r0 + NN / 8; r++) s += g_g[(size_t)r * HH + col];
    atomicAdd(&g_dln[col], s);
}

__global__ __launch_bounds__(256) void dln_sq() {
    float s = 0.f;
    for (int i = threadIdx.x; i < HH; i += 256) { float v = g_dln[i]; s += v * v; }
    s = block_sum(s);
    if (threadIdx.x == 0) atomicAdd(&g_gnorm, s);
}

__global__ __launch_bounds__(256) void update_params(int c) {
    float total = sqrtf(g_gnorm);
    float clip = fminf(1.0f / (total + 1e-6f), 1.0f);
    float eta = g_eta[c], beta = g_beta[c];
    const int n0 = II * HH, n1 = 2 * II * HH, nt = 2 * II * HH + HH;
    for (int i = blockIdx.x * blockDim.x + threadIdx.x; i < nt; i += gridDim.x * blockDim.x) {
        float *p, *sp;
        float gv;
        int j;
        if (i < n0) { j = i; p = g_w0; sp = g_s0; gv = g_dw0[j]; }
        else if (i < n1) { j = i - n0; p = g_w1; sp = g_s1; gv = g_dw1[j]; }
        else { j = i - n1; p = g_ln; sp = g_sln; gv = g_dln[j]; }
        float ns = eta * sp[j] - gv * clip;
        sp[j] = ns;
        p[j] = beta * p[j] + ns;
    }
}

__global__ __launch_bounds__(256) void final_out(float* __restrict__ out) {
    int r = blockIdx.x, t = threadIdx.x;
    float4 y4 = ((const float4*)(g_y2 + (size_t)r * HH))[t];
    float ss = y4.x * y4.x + y4.y * y4.y + y4.z * y4.z + y4.w * y4.w;
    ss = block_sum(ss);
    float rs = rsqrtf(ss / HH + 1e-6f);
    float4 q4 = ((const float4*)(g_q + (size_t)r * HH))[t];
    float4 l4 = ((const float4*)g_ln)[t];
    float4 o;
    o.x = q4.x + y4.x * rs * l4.x;
    o.y = q4.y + y4.y * rs * l4.y;
    o.z = q4.z + y4.z * rs * l4.z;
    o.w = q4.w + y4.w * rs * l4.w;
    ((float4*)(out + (size_t)r * HH))[t] = o;
}

// ---------------- host launcher ----------------
extern "C" void kernel_launch(void* const* d_in, const int* in_sizes, int n_in,
                              void* d_out, int out_size) {
    const float* x   = (const float*)d_in[0];
    const float* wq  = (const float*)d_in[1];
    const float* wk  = (const float*)d_in[2];
    const float* wv  = (const float*)d_in[3];
    const float* qn  = (const float*)d_in[4];
    const float* kn  = (const float*)d_in[5];
    const float* aw  = (const float*)d_in[6];
    const float* tw  = (const float*)d_in[7];
    const float* ew  = (const float*)d_in[8];
    const float* mw0 = (const float*)d_in[9];
    const float* mw1 = (const float*)d_in[10];
    const float* mln = (const float*)d_in[11];
    float* out = (float*)d_out;

    float *k_, *v_, *q_, *w0_, *w1_, *kc_, *z_, *h_, *dz_, *y_, *dy_, *dw0_, *dw1_, *h2_, *y2_;
    cudaGetSymbolAddress((void**)&k_,   g_k);
    cudaGetSymbolAddress((void**)&v_,   g_v);
    cudaGetSymbolAddress((void**)&q_,   g_q);
    cudaGetSymbolAddress((void**)&w0_,  g_w0);
    cudaGetSymbolAddress((void**)&w1_,  g_w1);
    cudaGetSymbolAddress((void**)&kc_,  g_kc);
    cudaGetSymbolAddress((void**)&z_,   g_z);
    cudaGetSymbolAddress((void**)&h_,   g_h);
    cudaGetSymbolAddress((void**)&dz_,  g_dz);
    cudaGetSymbolAddress((void**)&y_,   g_y);
    cudaGetSymbolAddress((void**)&dy_,  g_dy);
    cudaGetSymbolAddress((void**)&dw0_, g_dw0);
    cudaGetSymbolAddress((void**)&dw1_, g_dw1);
    cudaGetSymbolAddress((void**)&h2_,  g_h2);
    cudaGetSymbolAddress((void**)&y2_,  g_y2);

    // ---- init memory params + surprise state ----
    init_mem<<<1024, 256>>>(mw0, mw1, mln);

    // ---- precompute k, v, q (128x128 tiles, NT) ----
    dim3 gKVQ(HH / 128, NROWS / 128);
    gemm_tf32<128,128,64,32,8,true,true><<<gKVQ, 256>>>(x, wk, k_, nullptr, NROWS, HH, HH, EPI_SILU);
    rmsnorm_rows<<<NROWS, 256>>>(k_, kn);
    gemm_tf32<128,128,64,32,8,true,true><<<gKVQ, 256>>>(x, wv, v_, nullptr, NROWS, HH, HH, EPI_SILU);
    gemm_tf32<128,128,64,32,8,true,true><<<gKVQ, 256>>>(x, wq, q_, nullptr, NROWS, HH, HH, EPI_SILU);
    rmsnorm_rows<<<NROWS, 256>>>(q_, qn);

    // ---- adaptive coefficients ----
    coeff_dot<<<BB * NCH, 256>>>(x, aw, tw, ew);
    coeff_finalize<<<1, 256>>>();

    // ---- sequential scan over chunks ----
    for (int c = 0; c < NCH; c++) {
        gather_chunk<<<256, 256>>>(c);
        // z = kc @ w0^T ; h = silu(z)   (NT, 64-tile)
        gemm_tf32<64,64,32,32,4,true,true><<<dim3(II / 64, NN / 64), 128>>>(kc_, w0_, h_, z_, NN, II, HH, EPI_SILU_AUX);
        // y = h @ w1^T   (NT)
        gemm_tf32<64,64,32,32,4,true,true><<<dim3(HH / 64, NN / 64), 128>>>(h_, w1_, y_, nullptr, NN, HH, II, EPI_NONE);
        // backward through residual + rmsnorm + MSE
        chunk_bwd_y<<<NN, 256>>>(c);
        dln_partial<<<dim3(HH / 256, 8), 256>>>();
        dln_sq<<<1, 256>>>();
        // d_z = (d_y @ w1) * silu'(z)   (NN: A=dy MxK, B=w1 KxN)
        gemm_tf32<64,64,32,32,4,true,false><<<dim3(II / 64, NN / 64), 128>>>(dy_, w1_, dz_, z_, NN, II, HH, EPI_DSILU);
        // d_w1 = d_y^T @ h   (TN, 128-tile, fused grad sumsq)
        gemm_tf32<128,128,64,32,8,false,false><<<dim3(II / 128, HH / 128), 256>>>(dy_, h_, dw1_, nullptr, HH, II, NN, EPI_GRAD);
        // d_w0 = d_z^T @ kc  (TN, fused grad sumsq)
        gemm_tf32<128,128,64,32,8,false,false><<<dim3(HH / 128, II / 128), 256>>>(dz_, kc_, dw0_, nullptr, II, HH, NN, EPI_GRAD);
        // clipped EMA update
        update_params<<<1024, 256>>>(c);
    }

    // ---- retrieval with final memory ----
    gemm_tf32<128,128,64,32,8,true,true><<<dim3(II / 128, NROWS / 128), 256>>>(q_, w0_, h2_, nullptr, NROWS, II, HH, EPI_SILU);
    gemm_tf32<128,128,64,32,8,true,true><<<dim3(HH / 128, NROWS / 128), 256>>>(h2_, w1_, y2_, nullptr, NROWS, HH, II, EPI_NONE);
    final_out<<<NROWS, 256>>>(out);
}

// round 6
// speedup vs baseline: 2.3865x; 1.1764x over previous
#include <cuda_runtime.h>
#include <math.h>
#include <stdint.h>

#define BB 8
#define SS 2048
#define HH 1024
#define CC 64
#define NCH 32
#define NN 512      /* BB*CC rows per chunk */
#define II 2048     /* INTER */
#define NROWS 16384 /* BB*SS */

#define EPI_NONE 0
#define EPI_SILU 1
#define EPI_SILU_R 2
#define EPI_SILU_AUX_R 3
#define EPI_DSILU_R 4
#define EPI_GRAD 5
#define EPI_GRAD_LN 6

// ---------------- device scratch (no allocation allowed) ----------------
__device__ __align__(16) float g_k[NROWS * HH];
__device__ __align__(16) float g_v[NROWS * HH];
__device__ __align__(16) float g_q[NROWS * HH];
__device__ __align__(16) float g_qr[NROWS * HH];
__device__ __align__(16) float g_xr[NROWS * HH];
__device__ __align__(16) float g_wkr[HH * HH];
__device__ __align__(16) float g_wvr[HH * HH];
__device__ __align__(16) float g_wqr[HH * HH];
__device__ __align__(16) float g_kall[NROWS * HH];
__device__ __align__(16) float g_kallr[NROWS * HH];
__device__ __align__(16) float g_vall[NROWS * HH];
__device__ __align__(16) float g_w0[II * HH];
__device__ __align__(16) float g_w0r[II * HH];
__device__ __align__(16) float g_w1[HH * II];
__device__ __align__(16) float g_w1r[HH * II];
__device__ __align__(16) float g_ln[HH];
__device__ __align__(16) float g_s0[II * HH];
__device__ __align__(16) float g_s1[HH * II];
__device__ __align__(16) float g_sln[HH];
__device__ __align__(16) float g_z[NN * II];
__device__ __align__(16) float g_h[NN * II];
__device__ __align__(16) float g_dz[NN * II];
__device__ __align__(16) float g_y[NN * HH];
__device__ __align__(16) float g_dy[NN * HH];
__device__ __align__(16) float g_dw0[II * HH];
__device__ __align__(16) float g_dw1[HH * II];
__device__ __align__(16) float g_dlnA[NCH * HH];
__device__ __align__(16) float g_gnormA[NCH];
__device__ __align__(16) float g_h2[NROWS * II];
__device__ __align__(16) float g_y2[NROWS * HH];
__device__ __align__(16) float g_dotA[BB * NCH];
__device__ __align__(16) float g_dotT[BB * NCH];
__device__ __align__(16) float g_dotE[BB * NCH];
__device__ __align__(16) float g_beta[NCH];
__device__ __align__(16) float g_eta[NCH];
__device__ __align__(16) float g_theta[BB * NCH];

// ---------------- helpers ----------------
__device__ __forceinline__ float sigm(float x) { return 1.f / (1.f + expf(-x)); }
__device__ __forceinline__ float silu_f(float x) { return x / (1.f + expf(-x)); }
__device__ __forceinline__ float dsilu_f(float x) {
    float s = 1.f / (1.f + expf(-x));
    return s * (1.f + x * (1.f - s));
}
__device__ __forceinline__ uint32_t f2tf(float x) {
    uint32_t r;
    asm("cvt.rna.tf32.f32 %0, %1;" : "=r"(r) : "f"(x));
    return r;
}
__device__ __forceinline__ float rtf(float x) { return __uint_as_float(f2tf(x)); }

__device__ __forceinline__ void mma8(float* d, const uint32_t* a, const uint32_t* b) {
    asm volatile(
        "mma.sync.aligned.m16n8k8.row.col.f32.tf32.tf32.f32 "
        "{%0,%1,%2,%3}, {%4,%5,%6,%7}, {%8,%9}, {%0,%1,%2,%3};"
        : "+f"(d[0]), "+f"(d[1]), "+f"(d[2]), "+f"(d[3])
        : "r"(a[0]), "r"(a[1]), "r"(a[2]), "r"(a[3]), "r"(b[0]), "r"(b[1]));
}

__device__ __forceinline__ void cpa16(float* dst, const float* src) {
    uint32_t d = (uint32_t)__cvta_generic_to_shared(dst);
    asm volatile("cp.async.cg.shared.global [%0], [%1], 16;\n" :: "r"(d), "l"(src));
}
__device__ __forceinline__ void cpa_commit() { asm volatile("cp.async.commit_group;\n"); }

__device__ __forceinline__ float block_sum(float v) {
    __shared__ float sh[32];
    __shared__ float tot;
    int lane = threadIdx.x & 31;
    int w = threadIdx.x >> 5;
#pragma unroll
    for (int o = 16; o > 0; o >>= 1) v += __shfl_xor_sync(0xffffffffu, v, o);
    if (lane == 0) sh[w] = v;
    __syncthreads();
    if (w == 0) {
        float r = (lane < (blockDim.x >> 5)) ? sh[lane] : 0.f;
#pragma unroll
        for (int o = 16; o > 0; o >>= 1) r += __shfl_xor_sync(0xffffffffu, r, o);
        if (lane == 0) tot = r;
    }
    __syncthreads();
    return tot;
}

// ---------------- tf32 tensor-core GEMM (cp.async double-buffered) ----------------
// C[M,N] = opA(A) * opB(B).  Inputs must be pre-rounded to tf32.
//   AT=true : A is M x K row-major;   AT=false: A is K x M row-major (=A^T)
//   BT=true : B is N x K row-major;   BT=false: B is K x N row-major
template<int BM, int BN, int WM, int WN, int NWARP, bool AT, bool BT>
__global__ __launch_bounds__(NWARP * 32) void gemm_tc(
    const float* __restrict__ A, const float* __restrict__ B,
    float* __restrict__ C, float* __restrict__ aux, float* __restrict__ gn,
    int M, int N, int K, int epi)
{
    constexpr int NT = NWARP * 32;
    constexpr int SA = BM + 8;
    constexpr int SB = BN + 8;
    constexpr int ASZ = AT ? BM * 36 : 32 * SA;
    constexpr int BSZ = BT ? BN * 36 : 32 * SB;
    constexpr int PA = AT ? (BM * 8) / NT : (32 * (BM / 4)) / NT;
    constexpr int PB = BT ? (BN * 8) / NT : (32 * (BN / 4)) / NT;
    constexpr int WGM = BM / WM;
    constexpr int MI = WM / 16, NI = WN / 8;

    extern __shared__ float sm[];
    float* Ab[2] = { sm, sm + ASZ };
    float* Bb[2] = { sm + 2 * ASZ, sm + 2 * ASZ + BSZ };

    const int t = threadIdx.x;
    const int bm = blockIdx.y * BM, bn = blockIdx.x * BN;
    const int wid = t >> 5, lane = t & 31;
    const int wm = (wid % WGM) * WM;
    const int wn = (wid / WGM) * WN;
    const int gp = lane >> 2, kq = lane & 3;

    float acc[MI][NI][4];
#pragma unroll
    for (int i = 0; i < MI; i++)
#pragma unroll
        for (int j = 0; j < NI; j++)
#pragma unroll
            for (int q = 0; q < 4; q++) acc[i][j][q] = 0.f;

    auto issue = [&](int k0, int buf) {
        float* As = Ab[buf];
        float* Bs = Bb[buf];
#pragma unroll
        for (int p = 0; p < PA; p++) {
            int idx = p * NT + t;
            if constexpr (AT) {
                int row = idx >> 3, seg = idx & 7;
                cpa16(As + row * 36 + seg * 4, A + (size_t)(bm + row) * K + k0 + seg * 4);
            } else {
                int kk = idx / (BM / 4), mseg = idx % (BM / 4);
                cpa16(As + kk * SA + mseg * 4, A + (size_t)(k0 + kk) * M + bm + mseg * 4);
            }
        }
#pragma unroll
        for (int p = 0; p < PB; p++) {
            int idx = p * NT + t;
            if constexpr (BT) {
                int row = idx >> 3, seg = idx & 7;
                cpa16(Bs + row * 36 + seg * 4, B + (size_t)(bn + row) * K + k0 + seg * 4);
            } else {
                int kk = idx / (BN / 4), nseg = idx % (BN / 4);
                cpa16(Bs + kk * SB + nseg * 4, B + (size_t)(k0 + kk) * N + bn + nseg * 4);
            }
        }
        cpa_commit();
    };

    issue(0, 0);
    const int nit = K / 32;
    for (int it = 0; it < nit; it++) {
        if (it + 1 < nit) {
            issue((it + 1) * 32, (it + 1) & 1);
            asm volatile("cp.async.wait_group 1;\n");
        } else {
            asm volatile("cp.async.wait_group 0;\n");
        }
        __syncthreads();
        const float* As = Ab[it & 1];
        const float* Bs = Bb[it & 1];
#pragma unroll
        for (int ks = 0; ks < 4; ks++) {
            const int k8 = ks * 8 + kq;
            uint32_t af[MI][4], bf[NI][2];
#pragma unroll
            for (int mi = 0; mi < MI; mi++) {
                int r0 = wm + mi * 16 + gp;
                if constexpr (AT) {
                    af[mi][0] = __float_as_uint(As[r0 * 36 + k8]);
                    af[mi][1] = __float_as_uint(As[(r0 + 8) * 36 + k8]);
                    af[mi][2] = __float_as_uint(As[r0 * 36 + k8 + 4]);
                    af[mi][3] = __float_as_uint(As[(r0 + 8) * 36 + k8 + 4]);
                } else {
                    af[mi][0] = __float_as_uint(As[k8 * SA + r0]);
                    af[mi][1] = __float_as_uint(As[k8 * SA + r0 + 8]);
                    af[mi][2] = __float_as_uint(As[(k8 + 4) * SA + r0]);
                    af[mi][3] = __float_as_uint(As[(k8 + 4) * SA + r0 + 8]);
                }
            }
#pragma unroll
            for (int ni = 0; ni < NI; ni++) {
                int c0 = wn + ni * 8 + gp;
                if constexpr (BT) {
                    bf[ni][0] = __float_as_uint(Bs[c0 * 36 + k8]);
                    bf[ni][1] = __float_as_uint(Bs[c0 * 36 + k8 + 4]);
                } else {
                    bf[ni][0] = __float_as_uint(Bs[k8 * SB + c0]);
                    bf[ni][1] = __float_as_uint(Bs[(k8 + 4) * SB + c0]);
                }
            }
#pragma unroll
            for (int mi = 0; mi < MI; mi++)
#pragma unroll
                for (int ni = 0; ni < NI; ni++)
                    mma8(acc[mi][ni], af[mi], bf[ni]);
        }
        __syncthreads();
    }

    // epilogue
    float gs = 0.f;
#pragma unroll
    for (int mi = 0; mi < MI; mi++) {
#pragma unroll
        for (int ni = 0; ni < NI; ni++) {
            int r0 = bm + wm + mi * 16 + gp;
            int c = bn + wn + ni * 8 + kq * 2;
            size_t o0 = (size_t)r0 * N + c;
            size_t o1 = (size_t)(r0 + 8) * N + c;
            float2 v0 = make_float2(acc[mi][ni][0], acc[mi][ni][1]);
            float2 v1 = make_float2(acc[mi][ni][2], acc[mi][ni][3]);
            if (epi == EPI_SILU) {
                v0.x = silu_f(v0.x); v0.y = silu_f(v0.y);
                v1.x = silu_f(v1.x); v1.y = silu_f(v1.y);
            } else if (epi == EPI_SILU_R) {
                v0.x = rtf(silu_f(v0.x)); v0.y = rtf(silu_f(v0.y));
                v1.x = rtf(silu_f(v1.x)); v1.y = rtf(silu_f(v1.y));
            } else if (epi == EPI_SILU_AUX_R) {
                *(float2*)(aux + o0) = v0;
                *(float2*)(aux + o1) = v1;
                v0.x = rtf(silu_f(v0.x)); v0.y = rtf(silu_f(v0.y));
                v1.x = rtf(silu_f(v1.x)); v1.y = rtf(silu_f(v1.y));
            } else if (epi == EPI_DSILU_R) {
                float2 z0 = *(const float2*)(aux + o0);
                float2 z1 = *(const float2*)(aux + o1);
                v0.x = rtf(v0.x * dsilu_f(z0.x)); v0.y = rtf(v0.y * dsilu_f(z0.y));
                v1.x = rtf(v1.x * dsilu_f(z1.x)); v1.y = rtf(v1.y * dsilu_f(z1.y));
            } else if (epi >= EPI_GRAD) {
                gs += v0.x * v0.x + v0.y * v0.y + v1.x * v1.x + v1.y * v1.y;
            }
            *(float2*)(C + o0) = v0;
            *(float2*)(C + o1) = v1;
        }
    }
    if (epi >= EPI_GRAD) {
        gs = block_sum(gs);
        if (t == 0) atomicAdd(gn, gs);
        if (epi == EPI_GRAD_LN && blockIdx.x == 0 && blockIdx.y == 0) {
            float s = 0.f;
            for (int i = t; i < HH; i += NT) { float d = aux[i]; s += d * d; }
            s = block_sum(s);
            if (t == 0) atomicAdd(gn, s);
        }
    }
}

// ---------------- elementwise / reduction kernels ----------------
__global__ __launch_bounds__(256) void init_mem(
    const float* __restrict__ w0, const float* __restrict__ w1, const float* __restrict__ ln)
{
    int n = II * HH;
    for (int i = blockIdx.x * blockDim.x + threadIdx.x; i < n; i += gridDim.x * blockDim.x) {
        float a = w0[i]; g_w0[i] = a; g_w0r[i] = rtf(a); g_s0[i] = 0.f;
        float b = w1[i]; g_w1[i] = b; g_w1r[i] = rtf(b); g_s1[i] = 0.f;
        if (i < HH) { g_ln[i] = ln[i]; g_sln[i] = 0.f; }
        if (i < NCH * HH) g_dlnA[i] = 0.f;
        if (i < NCH) g_gnormA[i] = 0.f;
    }
}

__global__ __launch_bounds__(256) void round_copy(float* __restrict__ dst, const float* __restrict__ src, int n4) {
    for (int i = blockIdx.x * blockDim.x + threadIdx.x; i < n4; i += gridDim.x * blockDim.x) {
        float4 v = ((const float4*)src)[i];
        v.x = rtf(v.x); v.y = rtf(v.y); v.z = rtf(v.z); v.w = rtf(v.w);
        ((float4*)dst)[i] = v;
    }
}

__global__ __launch_bounds__(256) void rmsnorm_rows(float* __restrict__ buf, const float* __restrict__ w,
                                                    float* __restrict__ rout) {
    int r = blockIdx.x;
    int t = threadIdx.x;
    float4* row = (float4*)(buf + (size_t)r * HH);
    float4 v = row[t];
    float ss = v.x * v.x + v.y * v.y + v.z * v.z + v.w * v.w;
    ss = block_sum(ss);
    float rs = rsqrtf(ss / HH + 1e-6f);
    float4 wv = ((const float4*)w)[t];
    v.x *= rs * wv.x; v.y *= rs * wv.y; v.z *= rs * wv.z; v.w *= rs * wv.w;
    row[t] = v;
    if (rout) {
        float4 rv;
        rv.x = rtf(v.x); rv.y = rtf(v.y); rv.z = rtf(v.z); rv.w = rtf(v.w);
        ((float4*)(rout + (size_t)r * HH))[t] = rv;
    }
}

// gather all chunks once: kall (full), kallr (rounded), vall (full)
__global__ __launch_bounds__(256) void gather_all() {
    const int H4 = HH / 4;
    const int per = NN * H4;
    int ntot = NCH * per;
    for (int i = blockIdx.x * blockDim.x + threadIdx.x; i < ntot; i += gridDim.x * blockDim.x) {
        int c = i / per, rem = i - c * per;
        int m = rem / H4, q = rem - m * H4;
        int src = ((m >> 6) * SS + c * CC + (m & 63)) * H4 + q;
        float4 kv = ((const float4*)g_k)[src];
        ((float4*)g_kall)[i] = kv;
        float4 kr;
        kr.x = rtf(kv.x); kr.y = rtf(kv.y); kr.z = rtf(kv.z); kr.w = rtf(kv.w);
        ((float4*)g_kallr)[i] = kr;
        ((float4*)g_vall)[i] = ((const float4*)g_v)[src];
    }
}

__global__ __launch_bounds__(256) void coeff_dot(
    const float* __restrict__ x, const float* __restrict__ aw,
    const float* __restrict__ tw, const float* __restrict__ ew)
{
    int bc = blockIdx.x;
    int b = bc >> 5, nc = bc & 31;
    const float4* xf = (const float4*)(x + (size_t)(b * SS + nc * CC) * HH);
    const float4* a4 = (const float4*)aw;
    const float4* t4 = (const float4*)tw;
    const float4* e4 = (const float4*)ew;
    const int L4 = CC * HH / 4;
    float sa = 0.f, st = 0.f, se = 0.f;
    for (int i = threadIdx.x; i < L4; i += blockDim.x) {
        float4 xv = xf[i];
        float4 av = a4[i]; sa += xv.x * av.x + xv.y * av.y + xv.z * av.z + xv.w * av.w;
        float4 tv = t4[i]; st += xv.x * tv.x + xv.y * tv.y + xv.z * tv.z + xv.w * tv.w;
        float4 ev = e4[i]; se += xv.x * ev.x + xv.y * ev.y + xv.z * ev.z + xv.w * ev.w;
    }
    sa = block_sum(sa);
    st = block_sum(st);
    se = block_sum(se);
    if (threadIdx.x == 0) { g_dotA[bc] = sa; g_dotT[bc] = st; g_dotE[bc] = se; }
}

__global__ void coeff_finalize() {
    int t = threadIdx.x;
    if (t < BB * NCH) g_theta[t] = sigm(g_dotT[t]) * 0.01f;
    if (t < NCH) {
        float sa = 0.f, se = 0.f;
        for (int b = 0; b < BB; b++) { sa += g_dotA[b * NCH + t]; se += g_dotE[b * NCH + t]; }
        float al = sigm(sa / (float)BB);
        g_beta[t] = 1.f - al;
        g_eta[t] = sigm(se / (float)BB);
    }
}

// backward through rmsnorm + residual + weighted MSE; dy rounded; dln via atomics
__global__ __launch_bounds__(256) void chunk_bwd_y(int c) {
    int r = blockIdx.x;
    int t = threadIdx.x;
    int b = r >> 6;
    const float* kc = g_kall + (size_t)c * NN * HH;
    const float* vc = g_vall + (size_t)c * NN * HH;
    float4 y4 = ((const float4*)(g_y + (size_t)r * HH))[t];
    float ss = y4.x * y4.x + y4.y * y4.y + y4.z * y4.z + y4.w * y4.w;
    ss = block_sum(ss);
    float rs = rsqrtf(ss / HH + 1e-6f);
    float th = g_theta[b * NCH + c];
    float scale = 2.f * th / ((float)NN * (float)HH);
    float4 k4 = ((const float4*)(kc + (size_t)r * HH))[t];
    float4 v4 = ((const float4*)(vc + (size_t)r * HH))[t];
    float4 l4 = ((const float4*)g_ln)[t];
    float4 gg;
    gg.x = scale * (k4.x + y4.x * rs * l4.x - v4.x);
    gg.y = scale * (k4.y + y4.y * rs * l4.y - v4.y);
    gg.z = scale * (k4.z + y4.z * rs * l4.z - v4.z);
    gg.w = scale * (k4.w + y4.w * rs * l4.w - v4.w);
    float sv = gg.x * l4.x * y4.x + gg.y * l4.y * y4.y + gg.z * l4.z * y4.z + gg.w * l4.w * y4.w;
    sv = block_sum(sv);
    float c3 = rs * rs * rs * sv / (float)HH;
    float4 dy;
    dy.x = rtf(rs * gg.x * l4.x - c3 * y4.x);
    dy.y = rtf(rs * gg.y * l4.y - c3 * y4.y);
    dy.z = rtf(rs * gg.z * l4.z - c3 * y4.z);
    dy.w = rtf(rs * gg.w * l4.w - c3 * y4.w);
    ((float4*)(g_dy + (size_t)r * HH))[t] = dy;
    float* dln = g_dlnA + c * HH;
    atomicAdd(&dln[t * 4 + 0], gg.x * y4.x * rs);
    atomicAdd(&dln[t * 4 + 1], gg.y * y4.y * rs);
    atomicAdd(&dln[t * 4 + 2], gg.z * y4.z * rs);
    atomicAdd(&dln[t * 4 + 3], gg.w * y4.w * rs);
}

__global__ __launch_bounds__(256) void update_params(int c) {
    float total = sqrtf(g_gnormA[c]);
    float clip = fminf(1.0f / (total + 1e-6f), 1.0f);
    float eta = g_eta[c], beta = g_beta[c];
    const float* dln = g_dlnA + c * HH;
    const int n0 = II * HH, n1 = 2 * II * HH, nt = 2 * II * HH + HH;
    for (int i = blockIdx.x * blockDim.x + threadIdx.x; i < nt; i += gridDim.x * blockDim.x) {
        if (i < n0) {
            float ns = eta * g_s0[i] - g_dw0[i] * clip;
            g_s0[i] = ns;
            float nw = beta * g_w0[i] + ns;
            g_w0[i] = nw; g_w0r[i] = rtf(nw);
        } else if (i < n1) {
            int j = i - n0;
            float ns = eta * g_s1[j] - g_dw1[j] * clip;
            g_s1[j] = ns;
            float nw = beta * g_w1[j] + ns;
            g_w1[j] = nw; g_w1r[j] = rtf(nw);
        } else {
            int j = i - n1;
            float ns = eta * g_sln[j] - dln[j] * clip;
            g_sln[j] = ns;
            g_ln[j] = beta * g_ln[j] + ns;
        }
    }
}

__global__ __launch_bounds__(256) void final_out(float* __restrict__ out) {
    int r = blockIdx.x, t = threadIdx.x;
    float4 y4 = ((const float4*)(g_y2 + (size_t)r * HH))[t];
    float ss = y4.x * y4.x + y4.y * y4.y + y4.z * y4.z + y4.w * y4.w;
    ss = block_sum(ss);
    float rs = rsqrtf(ss / HH + 1e-6f);
    float4 q4 = ((const float4*)(g_q + (size_t)r * HH))[t];
    float4 l4 = ((const float4*)g_ln)[t];
    float4 o;
    o.x = q4.x + y4.x * rs * l4.x;
    o.y = q4.y + y4.y * rs * l4.y;
    o.z = q4.z + y4.z * rs * l4.z;
    o.w = q4.w + y4.w * rs * l4.w;
    ((float4*)(out + (size_t)r * HH))[t] = o;
}

// ---------------- host launcher ----------------
// G1: big NT   (128x256, warp 64x64)
// G2: scan NT  (64x128, warp 32x32)
// G3: scan NN  (64x128)
// G4: TN       (128x128, warp 64x32)
typedef void (*gemm_fn)(const float*, const float*, float*, float*, float*, int, int, int, int);

extern "C" void kernel_launch(void* const* d_in, const int* in_sizes, int n_in,
                              void* d_out, int out_size) {
    const float* x   = (const float*)d_in[0];
    const float* wq  = (const float*)d_in[1];
    const float* wk  = (const float*)d_in[2];
    const float* wv  = (const float*)d_in[3];
    const float* qn  = (const float*)d_in[4];
    const float* kn  = (const float*)d_in[5];
    const float* aw  = (const float*)d_in[6];
    const float* tw  = (const float*)d_in[7];
    const float* ew  = (const float*)d_in[8];
    const float* mw0 = (const float*)d_in[9];
    const float* mw1 = (const float*)d_in[10];
    const float* mln = (const float*)d_in[11];
    float* out = (float*)d_out;

    float *k_, *v_, *q_, *qr_, *xr_, *wkr_, *wvr_, *wqr_;
    float *w0r_, *w1r_, *kallr_, *z_, *h_, *dz_, *y_, *dy_, *dw0_, *dw1_, *dlnA_, *gnA_, *h2_, *y2_;
    cudaGetSymbolAddress((void**)&k_,    g_k);
    cudaGetSymbolAddress((void**)&v_,    g_v);
    cudaGetSymbolAddress((void**)&q_,    g_q);
    cudaGetSymbolAddress((void**)&qr_,   g_qr);
    cudaGetSymbolAddress((void**)&xr_,   g_xr);
    cudaGetSymbolAddress((void**)&wkr_,  g_wkr);
    cudaGetSymbolAddress((void**)&wvr_,  g_wvr);
    cudaGetSymbolAddress((void**)&wqr_,  g_wqr);
    cudaGetSymbolAddress((void**)&w0r_,  g_w0r);
    cudaGetSymbolAddress((void**)&w1r_,  g_w1r);
    cudaGetSymbolAddress((void**)&kallr_,g_kallr);
    cudaGetSymbolAddress((void**)&z_,    g_z);
    cudaGetSymbolAddress((void**)&h_,    g_h);
    cudaGetSymbolAddress((void**)&dz_,   g_dz);
    cudaGetSymbolAddress((void**)&y_,    g_y);
    cudaGetSymbolAddress((void**)&dy_,   g_dy);
    cudaGetSymbolAddress((void**)&dw0_,  g_dw0);
    cudaGetSymbolAddress((void**)&dw1_,  g_dw1);
    cudaGetSymbolAddress((void**)&dlnA_, g_dlnA);
    cudaGetSymbolAddress((void**)&gnA_,  g_gnormA);
    cudaGetSymbolAddress((void**)&h2_,   g_h2);
    cudaGetSymbolAddress((void**)&y2_,   g_y2);

    // template instantiations + dynamic smem sizes
    auto G1 = gemm_tc<128,256,64,64,8,true,true>;
    auto G2 = gemm_tc<64,128,32,32,8,true,true>;
    auto G3 = gemm_tc<64,128,32,32,8,true,false>;
    auto G4 = gemm_tc<128,128,64,32,8,false,false>;
    const int S1 = 2 * (128*36 + 256*36) * 4;           // 110592
    const int S2 = 2 * (64*36 + 128*36) * 4;            // 55296
    const int S3 = 2 * (64*36 + 32*136) * 4;            // 53248
    const int S4 = 2 * (32*136 + 32*136) * 4;           // 69632
    static int attr_done = 0;
    if (!attr_done) {
        cudaFuncSetAttribute(G1, cudaFuncAttributeMaxDynamicSharedMemorySize, S1);
        cudaFuncSetAttribute(G2, cudaFuncAttributeMaxDynamicSharedMemorySize, S2);
        cudaFuncSetAttribute(G3, cudaFuncAttributeMaxDynamicSharedMemorySize, S3);
        cudaFuncSetAttribute(G4, cudaFuncAttributeMaxDynamicSharedMemorySize, S4);
        attr_done = 1;
    }

    // ---- init + pre-round inputs ----
    init_mem<<<2048, 256>>>(mw0, mw1, mln);
    round_copy<<<2048, 256>>>(xr_, x, NROWS * HH / 4);
    round_copy<<<512, 256>>>(wkr_, wk, HH * HH / 4);
    round_copy<<<512, 256>>>(wvr_, wv, HH * HH / 4);
    round_copy<<<512, 256>>>(wqr_, wq, HH * HH / 4);

    // ---- precompute k, v, q ----
    dim3 gKVQ(HH / 256, NROWS / 128);
    G1<<<gKVQ, 256, S1>>>(xr_, wkr_, k_, nullptr, nullptr, NROWS, HH, HH, EPI_SILU);
    rmsnorm_rows<<<NROWS, 256>>>(k_, kn, nullptr);
    G1<<<gKVQ, 256, S1>>>(xr_, wvr_, v_, nullptr, nullptr, NROWS, HH, HH, EPI_SILU);
    G1<<<gKVQ, 256, S1>>>(xr_, wqr_, q_, nullptr, nullptr, NROWS, HH, HH, EPI_SILU);
    rmsnorm_rows<<<NROWS, 256>>>(q_, qn, qr_);
    gather_all<<<2048, 256>>>();

    // ---- adaptive coefficients ----
    coeff_dot<<<BB * NCH, 256>>>(x, aw, tw, ew);
    coeff_finalize<<<1, 256>>>();

    // ---- sequential scan over chunks ----
    for (int c = 0; c < NCH; c++) {
        const float* kcr = kallr_ + (size_t)c * NN * HH;
        // z = kc @ w0^T ; h = round(silu(z)), aux z full
        G2<<<dim3(II / 128, NN / 64), 256, S2>>>(kcr, w0r_, h_, z_, nullptr, NN, II, HH, EPI_SILU_AUX_R);
        // y = h @ w1^T
        G2<<<dim3(HH / 128, NN / 64), 256, S2>>>(h_, w1r_, y_, nullptr, nullptr, NN, HH, II, EPI_NONE);
        // backward through residual + rmsnorm + MSE (dln atomics)
        chunk_bwd_y<<<NN, 256>>>(c);
        // d_z = (d_y @ w1) * silu'(z), rounded
        G3<<<dim3(II / 128, NN / 64), 256, S3>>>(dy_, w1r_, dz_, z_, nullptr, NN, II, HH, EPI_DSILU_R);
        // d_w1 = d_y^T @ h (TN, fused grad sumsq)
        G4<<<dim3(II / 128, HH / 128), 256, S4>>>(dy_, h_, dw1_, nullptr, gnA_ + c, HH, II, NN, EPI_GRAD);
        // d_w0 = d_z^T @ kc (TN, fused grad sumsq + dln^2)
        G4<<<dim3(HH / 128, II / 128), 256, S4>>>(dz_, kcr, dw0_, dlnA_ + c * HH, gnA_ + c, II, HH, NN, EPI_GRAD_LN);
        // clipped EMA update (+ rounded weight copies)
        update_params<<<1024, 256>>>(c);
    }

    // ---- retrieval with final memory ----
    G1<<<dim3(II / 256, NROWS / 128), 256, S1>>>(qr_, w0r_, h2_, nullptr, nullptr, NROWS, II, HH, EPI_SILU_R);
    G1<<<dim3(HH / 256, NROWS / 128), 256, S1>>>(h2_, w1r_, y2_, nullptr, nullptr, NROWS, HH, II, EPI_NONE);
    final_out<<<NROWS, 256>>>(out);
}

// round 7
// speedup vs baseline: 2.5435x; 1.0658x over previous
#include <cuda_runtime.h>
#include <math.h>
#include <stdint.h>

#define BB 8
#define SS 2048
#define HH 1024
#define CC 64
#define NCH 32
#define NN 512      /* BB*CC rows per chunk */
#define II 2048     /* INTER */
#define NROWS 16384 /* BB*SS */

#define EPI_NONE 0
#define EPI_SILU 1
#define EPI_SILU_R 2
#define EPI_SILU_AUX_R 3
#define EPI_DSILU_R 4
#define EPI_GRAD 5
#define EPI_GRAD_LN 6

// ---------------- device scratch (no allocation allowed) ----------------
__device__ __align__(16) float g_k[NROWS * HH];
__device__ __align__(16) float g_v[NROWS * HH];
__device__ __align__(16) float g_q[NROWS * HH];
__device__ __align__(16) float g_qr[NROWS * HH];
__device__ __align__(16) float g_xr[NROWS * HH];
__device__ __align__(16) float g_wkr[HH * HH];
__device__ __align__(16) float g_wvr[HH * HH];
__device__ __align__(16) float g_wqr[HH * HH];
__device__ __align__(16) float g_kall[NROWS * HH];
__device__ __align__(16) float g_kallr[NROWS * HH];
__device__ __align__(16) float g_vall[NROWS * HH];
__device__ __align__(16) float g_w0[II * HH];
__device__ __align__(16) float g_w0r[II * HH];
__device__ __align__(16) float g_w1[HH * II];
__device__ __align__(16) float g_w1r[HH * II];
__device__ __align__(16) float g_ln[HH];
__device__ __align__(16) float g_s0[II * HH];
__device__ __align__(16) float g_s1[HH * II];
__device__ __align__(16) float g_sln[HH];
__device__ __align__(16) float g_z[NN * II];
__device__ __align__(16) float g_h[NN * II];
__device__ __align__(16) float g_dz[NN * II];
__device__ __align__(16) float g_y[NN * HH];
__device__ __align__(16) float g_dy[NN * HH];
__device__ __align__(16) float g_dw0[II * HH];
__device__ __align__(16) float g_dw1[HH * II];
__device__ __align__(16) float g_dlnA[NCH * HH];
__device__ __align__(16) float g_gnormA[NCH];
__device__ __align__(16) float g_h2[NROWS * II];
__device__ __align__(16) float g_y2[NROWS * HH];
__device__ __align__(16) float g_dotA[BB * NCH];
__device__ __align__(16) float g_dotT[BB * NCH];
__device__ __align__(16) float g_dotE[BB * NCH];
__device__ __align__(16) float g_beta[NCH];
__device__ __align__(16) float g_eta[NCH];
__device__ __align__(16) float g_theta[BB * NCH];

// ---------------- helpers ----------------
__device__ __forceinline__ float sigm(float x) { return 1.f / (1.f + expf(-x)); }
__device__ __forceinline__ float silu_f(float x) { return x / (1.f + expf(-x)); }
__device__ __forceinline__ float dsilu_f(float x) {
    float s = 1.f / (1.f + expf(-x));
    return s * (1.f + x * (1.f - s));
}
__device__ __forceinline__ uint32_t f2tf(float x) {
    uint32_t r;
    asm("cvt.rna.tf32.f32 %0, %1;" : "=r"(r) : "f"(x));
    return r;
}
__device__ __forceinline__ float rtf(float x) { return __uint_as_float(f2tf(x)); }

__device__ __forceinline__ void mma8(float* d, const uint32_t* a, const uint32_t* b) {
    asm volatile(
        "mma.sync.aligned.m16n8k8.row.col.f32.tf32.tf32.f32 "
        "{%0,%1,%2,%3}, {%4,%5,%6,%7}, {%8,%9}, {%0,%1,%2,%3};"
        : "+f"(d[0]), "+f"(d[1]), "+f"(d[2]), "+f"(d[3])
        : "r"(a[0]), "r"(a[1]), "r"(a[2]), "r"(a[3]), "r"(b[0]), "r"(b[1]));
}

__device__ __forceinline__ void cpa16(float* dst, const float* src) {
    uint32_t d = (uint32_t)__cvta_generic_to_shared(dst);
    asm volatile("cp.async.cg.shared.global [%0], [%1], 16;\n" :: "r"(d), "l"(src));
}
__device__ __forceinline__ void cpa_commit() { asm volatile("cp.async.commit_group;\n"); }

__device__ __forceinline__ float block_sum(float v) {
    __shared__ float sh[32];
    __shared__ float tot;
    int lane = threadIdx.x & 31;
    int w = threadIdx.x >> 5;
#pragma unroll
    for (int o = 16; o > 0; o >>= 1) v += __shfl_xor_sync(0xffffffffu, v, o);
    if (lane == 0) sh[w] = v;
    __syncthreads();
    if (w == 0) {
        float r = (lane < (blockDim.x >> 5)) ? sh[lane] : 0.f;
#pragma unroll
        for (int o = 16; o > 0; o >>= 1) r += __shfl_xor_sync(0xffffffffu, r, o);
        if (lane == 0) tot = r;
    }
    __syncthreads();
    return tot;
}

// ---------------- tf32 tensor-core GEMM body (cp.async double-buffered) --------
// C[M,N] = opA(A) * opB(B).  Inputs must be pre-rounded to tf32.
//   AT=true : A is M x K row-major;   AT=false: A is K x M row-major (=A^T)
//   BT=true : B is N x K row-major;   BT=false: B is K x N row-major
template<int BM, int BN, int WM, int WN, int NWARP, bool AT, bool BT>
__device__ __forceinline__ void gemm_body(
    float* sm,
    const float* __restrict__ A, const float* __restrict__ B,
    float* __restrict__ C, float* __restrict__ aux, float* __restrict__ gn,
    int M, int N, int K, int epi, int bx, int by)
{
    constexpr int NT = NWARP * 32;
    constexpr int SA = BM + 8;
    constexpr int SB = BN + 8;
    constexpr int ASZ = AT ? BM * 36 : 32 * SA;
    constexpr int BSZ = BT ? BN * 36 : 32 * SB;
    constexpr int PA = AT ? (BM * 8) / NT : (32 * (BM / 4)) / NT;
    constexpr int PB = BT ? (BN * 8) / NT : (32 * (BN / 4)) / NT;
    constexpr int WGM = BM / WM;
    constexpr int MI = WM / 16, NI = WN / 8;

    float* Ab[2] = { sm, sm + ASZ };
    float* Bb[2] = { sm + 2 * ASZ, sm + 2 * ASZ + BSZ };

    const int t = threadIdx.x;
    const int bm = by * BM, bn = bx * BN;
    const int wid = t >> 5, lane = t & 31;
    const int wm = (wid % WGM) * WM;
    const int wn = (wid / WGM) * WN;
    const int gp = lane >> 2, kq = lane & 3;

    float acc[MI][NI][4];
#pragma unroll
    for (int i = 0; i < MI; i++)
#pragma unroll
        for (int j = 0; j < NI; j++)
#pragma unroll
            for (int q = 0; q < 4; q++) acc[i][j][q] = 0.f;

    auto issue = [&](int k0, int buf) {
        float* As = Ab[buf];
        float* Bs = Bb[buf];
#pragma unroll
        for (int p = 0; p < PA; p++) {
            int idx = p * NT + t;
            if constexpr (AT) {
                int row = idx >> 3, seg = idx & 7;
                cpa16(As + row * 36 + seg * 4, A + (size_t)(bm + row) * K + k0 + seg * 4);
            } else {
                int kk = idx / (BM / 4), mseg = idx % (BM / 4);
                cpa16(As + kk * SA + mseg * 4, A + (size_t)(k0 + kk) * M + bm + mseg * 4);
            }
        }
#pragma unroll
        for (int p = 0; p < PB; p++) {
            int idx = p * NT + t;
            if constexpr (BT) {
                int row = idx >> 3, seg = idx & 7;
                cpa16(Bs + row * 36 + seg * 4, B + (size_t)(bn + row) * K + k0 + seg * 4);
            } else {
                int kk = idx / (BN / 4), nseg = idx % (BN / 4);
                cpa16(Bs + kk * SB + nseg * 4, B + (size_t)(k0 + kk) * N + bn + nseg * 4);
            }
        }
        cpa_commit();
    };

    issue(0, 0);
    const int nit = K / 32;
    for (int it = 0; it < nit; it++) {
        if (it + 1 < nit) {
            issue((it + 1) * 32, (it + 1) & 1);
            asm volatile("cp.async.wait_group 1;\n");
        } else {
            asm volatile("cp.async.wait_group 0;\n");
        }
        __syncthreads();
        const float* As = Ab[it & 1];
        const float* Bs = Bb[it & 1];
#pragma unroll
        for (int ks = 0; ks < 4; ks++) {
            const int k8 = ks * 8 + kq;
            uint32_t af[MI][4], bf[NI][2];
#pragma unroll
            for (int mi = 0; mi < MI; mi++) {
                int r0 = wm + mi * 16 + gp;
                if constexpr (AT) {
                    af[mi][0] = __float_as_uint(As[r0 * 36 + k8]);
                    af[mi][1] = __float_as_uint(As[(r0 + 8) * 36 + k8]);
                    af[mi][2] = __float_as_uint(As[r0 * 36 + k8 + 4]);
                    af[mi][3] = __float_as_uint(As[(r0 + 8) * 36 + k8 + 4]);
                } else {
                    af[mi][0] = __float_as_uint(As[k8 * SA + r0]);
                    af[mi][1] = __float_as_uint(As[k8 * SA + r0 + 8]);
                    af[mi][2] = __float_as_uint(As[(k8 + 4) * SA + r0]);
                    af[mi][3] = __float_as_uint(As[(k8 + 4) * SA + r0 + 8]);
                }
            }
#pragma unroll
            for (int ni = 0; ni < NI; ni++) {
                int c0 = wn + ni * 8 + gp;
                if constexpr (BT) {
                    bf[ni][0] = __float_as_uint(Bs[c0 * 36 + k8]);
                    bf[ni][1] = __float_as_uint(Bs[c0 * 36 + k8 + 4]);
                } else {
                    bf[ni][0] = __float_as_uint(Bs[k8 * SB + c0]);
                    bf[ni][1] = __float_as_uint(Bs[(k8 + 4) * SB + c0]);
                }
            }
#pragma unroll
            for (int mi = 0; mi < MI; mi++)
#pragma unroll
                for (int ni = 0; ni < NI; ni++)
                    mma8(acc[mi][ni], af[mi], bf[ni]);
        }
        __syncthreads();
    }

    // epilogue
    float gs = 0.f;
#pragma unroll
    for (int mi = 0; mi < MI; mi++) {
#pragma unroll
        for (int ni = 0; ni < NI; ni++) {
            int r0 = bm + wm + mi * 16 + gp;
            int c = bn + wn + ni * 8 + kq * 2;
            size_t o0 = (size_t)r0 * N + c;
            size_t o1 = (size_t)(r0 + 8) * N + c;
            float2 v0 = make_float2(acc[mi][ni][0], acc[mi][ni][1]);
            float2 v1 = make_float2(acc[mi][ni][2], acc[mi][ni][3]);
            if (epi == EPI_SILU) {
                v0.x = silu_f(v0.x); v0.y = silu_f(v0.y);
                v1.x = silu_f(v1.x); v1.y = silu_f(v1.y);
            } else if (epi == EPI_SILU_R) {
                v0.x = rtf(silu_f(v0.x)); v0.y = rtf(silu_f(v0.y));
                v1.x = rtf(silu_f(v1.x)); v1.y = rtf(silu_f(v1.y));
            } else if (epi == EPI_SILU_AUX_R) {
                *(float2*)(aux + o0) = v0;
                *(float2*)(aux + o1) = v1;
                v0.x = rtf(silu_f(v0.x)); v0.y = rtf(silu_f(v0.y));
                v1.x = rtf(silu_f(v1.x)); v1.y = rtf(silu_f(v1.y));
            } else if (epi == EPI_DSILU_R) {
                float2 z0 = *(const float2*)(aux + o0);
                float2 z1 = *(const float2*)(aux + o1);
                v0.x = rtf(v0.x * dsilu_f(z0.x)); v0.y = rtf(v0.y * dsilu_f(z0.y));
                v1.x = rtf(v1.x * dsilu_f(z1.x)); v1.y = rtf(v1.y * dsilu_f(z1.y));
            } else if (epi >= EPI_GRAD) {
                gs += v0.x * v0.x + v0.y * v0.y + v1.x * v1.x + v1.y * v1.y;
            }
            *(float2*)(C + o0) = v0;
            *(float2*)(C + o1) = v1;
        }
    }
    if (epi >= EPI_GRAD) {
        gs = block_sum(gs);
        if (t == 0) atomicAdd(gn, gs);
        if (epi == EPI_GRAD_LN && bx == 0 && by == 0) {
            float s = 0.f;
            for (int i = t; i < HH; i += NT) { float d = aux[i]; s += d * d; }
            s = block_sum(s);
            if (t == 0) atomicAdd(gn, s);
        }
    }
}

template<int BM, int BN, int WM, int WN, int NWARP, bool AT, bool BT>
__global__ __launch_bounds__(NWARP * 32) void gemm_tc(
    const float* __restrict__ A, const float* __restrict__ B,
    float* __restrict__ C, float* __restrict__ aux, float* __restrict__ gn,
    int M, int N, int K, int epi)
{
    extern __shared__ float sm[];
    gemm_body<BM, BN, WM, WN, NWARP, AT, BT>(sm, A, B, C, aux, gn, M, N, K, epi,
                                             blockIdx.x, blockIdx.y);
}

// fused: blockIdx.z==0 -> dz = (dy @ w1) * silu'(z)   [64x128 tiles, grid 16x8]
//        blockIdx.z==1 -> dw1 = dy^T @ h + grad sumsq  [128x128 tiles, grid 16x8]
__global__ __launch_bounds__(128) void fused_dz_dw1(
    const float* __restrict__ dy, const float* __restrict__ w1r,
    float* __restrict__ dz, float* __restrict__ z,
    const float* __restrict__ h, float* __restrict__ dw1, float* __restrict__ gn)
{
    extern __shared__ float sm[];
    if (blockIdx.z == 0)
        gemm_body<64, 128, 32, 64, 4, true, false>(sm, dy, w1r, dz, z, nullptr,
                                                   NN, II, HH, EPI_DSILU_R,
                                                   blockIdx.x, blockIdx.y);
    else
        gemm_body<128, 128, 64, 64, 4, false, false>(sm, dy, h, dw1, nullptr, gn,
                                                     HH, II, NN, EPI_GRAD,
                                                     blockIdx.x, blockIdx.y);
}

// ---------------- elementwise / reduction kernels ----------------
__global__ __launch_bounds__(256) void init_mem(
    const float* __restrict__ w0, const float* __restrict__ w1, const float* __restrict__ ln)
{
    int n = II * HH;
    for (int i = blockIdx.x * blockDim.x + threadIdx.x; i < n; i += gridDim.x * blockDim.x) {
        float a = w0[i]; g_w0[i] = a; g_w0r[i] = rtf(a); g_s0[i] = 0.f;
        float b = w1[i]; g_w1[i] = b; g_w1r[i] = rtf(b); g_s1[i] = 0.f;
        if (i < HH) { g_ln[i] = ln[i]; g_sln[i] = 0.f; }
        if (i < NCH * HH) g_dlnA[i] = 0.f;
        if (i < NCH) g_gnormA[i] = 0.f;
    }
}

__global__ __launch_bounds__(256) void round_copy(float* __restrict__ dst, const float* __restrict__ src, int n4) {
    for (int i = blockIdx.x * blockDim.x + threadIdx.x; i < n4; i += gridDim.x * blockDim.x) {
        float4 v = ((const float4*)src)[i];
        v.x = rtf(v.x); v.y = rtf(v.y); v.z = rtf(v.z); v.w = rtf(v.w);
        ((float4*)dst)[i] = v;
    }
}

__global__ __launch_bounds__(256) void rmsnorm_rows(float* __restrict__ buf, const float* __restrict__ w,
                                                    float* __restrict__ rout) {
    int r = blockIdx.x;
    int t = threadIdx.x;
    float4* row = (float4*)(buf + (size_t)r * HH);
    float4 v = row[t];
    float ss = v.x * v.x + v.y * v.y + v.z * v.z + v.w * v.w;
    ss = block_sum(ss);
    float rs = rsqrtf(ss / HH + 1e-6f);
    float4 wv = ((const float4*)w)[t];
    v.x *= rs * wv.x; v.y *= rs * wv.y; v.z *= rs * wv.z; v.w *= rs * wv.w;
    row[t] = v;
    if (rout) {
        float4 rv;
        rv.x = rtf(v.x); rv.y = rtf(v.y); rv.z = rtf(v.z); rv.w = rtf(v.w);
        ((float4*)(rout + (size_t)r * HH))[t] = rv;
    }
}

// gather all chunks once: kall (full), kallr (rounded), vall (full)
__global__ __launch_bounds__(256) void gather_all() {
    const int H4 = HH / 4;
    const int per = NN * H4;
    int ntot = NCH * per;
    for (int i = blockIdx.x * blockDim.x + threadIdx.x; i < ntot; i += gridDim.x * blockDim.x) {
        int c = i / per, rem = i - c * per;
        int m = rem / H4, q = rem - m * H4;
        int src = ((m >> 6) * SS + c * CC + (m & 63)) * H4 + q;
        float4 kv = ((const float4*)g_k)[src];
        ((float4*)g_kall)[i] = kv;
        float4 kr;
        kr.x = rtf(kv.x); kr.y = rtf(kv.y); kr.z = rtf(kv.z); kr.w = rtf(kv.w);
        ((float4*)g_kallr)[i] = kr;
        ((float4*)g_vall)[i] = ((const float4*)g_v)[src];
    }
}

__global__ __launch_bounds__(256) void coeff_dot(
    const float* __restrict__ x, const float* __restrict__ aw,
    const float* __restrict__ tw, const float* __restrict__ ew)
{
    int bc = blockIdx.x;
    int b = bc >> 5, nc = bc & 31;
    const float4* xf = (const float4*)(x + (size_t)(b * SS + nc * CC) * HH);
    const float4* a4 = (const float4*)aw;
    const float4* t4 = (const float4*)tw;
    const float4* e4 = (const float4*)ew;
    const int L4 = CC * HH / 4;
    float sa = 0.f, st = 0.f, se = 0.f;
    for (int i = threadIdx.x; i < L4; i += blockDim.x) {
        float4 xv = xf[i];
        float4 av = a4[i]; sa += xv.x * av.x + xv.y * av.y + xv.z * av.z + xv.w * av.w;
        float4 tv = t4[i]; st += xv.x * tv.x + xv.y * tv.y + xv.z * tv.z + xv.w * tv.w;
        float4 ev = e4[i]; se += xv.x * ev.x + xv.y * ev.y + xv.z * ev.z + xv.w * ev.w;
    }
    sa = block_sum(sa);
    st = block_sum(st);
    se = block_sum(se);
    if (threadIdx.x == 0) { g_dotA[bc] = sa; g_dotT[bc] = st; g_dotE[bc] = se; }
}

__global__ void coeff_finalize() {
    int t = threadIdx.x;
    if (t < BB * NCH) g_theta[t] = sigm(g_dotT[t]) * 0.01f;
    if (t < NCH) {
        float sa = 0.f, se = 0.f;
        for (int b = 0; b < BB; b++) { sa += g_dotA[b * NCH + t]; se += g_dotE[b * NCH + t]; }
        float al = sigm(sa / (float)BB);
        g_beta[t] = 1.f - al;
        g_eta[t] = sigm(se / (float)BB);
    }
}

// backward through rmsnorm + residual + weighted MSE; dy rounded; dln via atomics
__global__ __launch_bounds__(256) void chunk_bwd_y(int c) {
    int r = blockIdx.x;
    int t = threadIdx.x;
    int b = r >> 6;
    const float* kc = g_kall + (size_t)c * NN * HH;
    const float* vc = g_vall + (size_t)c * NN * HH;
    float4 y4 = ((const float4*)(g_y + (size_t)r * HH))[t];
    float ss = y4.x * y4.x + y4.y * y4.y + y4.z * y4.z + y4.w * y4.w;
    ss = block_sum(ss);
    float rs = rsqrtf(ss / HH + 1e-6f);
    float th = g_theta[b * NCH + c];
    float scale = 2.f * th / ((float)NN * (float)HH);
    float4 k4 = ((const float4*)(kc + (size_t)r * HH))[t];
    float4 v4 = ((const float4*)(vc + (size_t)r * HH))[t];
    float4 l4 = ((const float4*)g_ln)[t];
    float4 gg;
    gg.x = scale * (k4.x + y4.x * rs * l4.x - v4.x);
    gg.y = scale * (k4.y + y4.y * rs * l4.y - v4.y);
    gg.z = scale * (k4.z + y4.z * rs * l4.z - v4.z);
    gg.w = scale * (k4.w + y4.w * rs * l4.w - v4.w);
    float sv = gg.x * l4.x * y4.x + gg.y * l4.y * y4.y + gg.z * l4.z * y4.z + gg.w * l4.w * y4.w;
    sv = block_sum(sv);
    float c3 = rs * rs * rs * sv / (float)HH;
    float4 dy;
    dy.x = rtf(rs * gg.x * l4.x - c3 * y4.x);
    dy.y = rtf(rs * gg.y * l4.y - c3 * y4.y);
    dy.z = rtf(rs * gg.z * l4.z - c3 * y4.z);
    dy.w = rtf(rs * gg.w * l4.w - c3 * y4.w);
    ((float4*)(g_dy + (size_t)r * HH))[t] = dy;
    float* dln = g_dlnA + c * HH;
    atomicAdd(&dln[t * 4 + 0], gg.x * y4.x * rs);
    atomicAdd(&dln[t * 4 + 1], gg.y * y4.y * rs);
    atomicAdd(&dln[t * 4 + 2], gg.z * y4.z * rs);
    atomicAdd(&dln[t * 4 + 3], gg.w * y4.w * rs);
}

__global__ __launch_bounds__(256) void update_params(int c) {
    float total = sqrtf(g_gnormA[c]);
    float clip = fminf(1.0f / (total + 1e-6f), 1.0f);
    float eta = g_eta[c], beta = g_beta[c];
    const float* dln = g_dlnA + c * HH;
    const int n0 = II * HH, n1 = 2 * II * HH, nt = 2 * II * HH + HH;
    for (int i = blockIdx.x * blockDim.x + threadIdx.x; i < nt; i += gridDim.x * blockDim.x) {
        if (i < n0) {
            float ns = eta * g_s0[i] - g_dw0[i] * clip;
            g_s0[i] = ns;
            float nw = beta * g_w0[i] + ns;
            g_w0[i] = nw; g_w0r[i] = rtf(nw);
        } else if (i < n1) {
            int j = i - n0;
            float ns = eta * g_s1[j] - g_dw1[j] * clip;
            g_s1[j] = ns;
            float nw = beta * g_w1[j] + ns;
            g_w1[j] = nw; g_w1r[j] = rtf(nw);
        } else {
            int j = i - n1;
            float ns = eta * g_sln[j] - dln[j] * clip;
            g_sln[j] = ns;
            g_ln[j] = beta * g_ln[j] + ns;
        }
    }
}

__global__ __launch_bounds__(256) void final_out(float* __restrict__ out) {
    int r = blockIdx.x, t = threadIdx.x;
    float4 y4 = ((const float4*)(g_y2 + (size_t)r * HH))[t];
    float ss = y4.x * y4.x + y4.y * y4.y + y4.z * y4.z + y4.w * y4.w;
    ss = block_sum(ss);
    float rs = rsqrtf(ss / HH + 1e-6f);
    float4 q4 = ((const float4*)(g_q + (size_t)r * HH))[t];
    float4 l4 = ((const float4*)g_ln)[t];
    float4 o;
    o.x = q4.x + y4.x * rs * l4.x;
    o.y = q4.y + y4.y * rs * l4.y;
    o.z = q4.z + y4.z * rs * l4.z;
    o.w = q4.w + y4.w * rs * l4.w;
    ((float4*)(out + (size_t)r * HH))[t] = o;
}

// ---------------- host launcher ----------------
extern "C" void kernel_launch(void* const* d_in, const int* in_sizes, int n_in,
                              void* d_out, int out_size) {
    const float* x   = (const float*)d_in[0];
    const float* wq  = (const float*)d_in[1];
    const float* wk  = (const float*)d_in[2];
    const float* wv  = (const float*)d_in[3];
    const float* qn  = (const float*)d_in[4];
    const float* kn  = (const float*)d_in[5];
    const float* aw  = (const float*)d_in[6];
    const float* tw  = (const float*)d_in[7];
    const float* ew  = (const float*)d_in[8];
    const float* mw0 = (const float*)d_in[9];
    const float* mw1 = (const float*)d_in[10];
    const float* mln = (const float*)d_in[11];
    float* out = (float*)d_out;

    float *k_, *v_, *q_, *qr_, *xr_, *wkr_, *wvr_, *wqr_;
    float *w0r_, *w1r_, *kallr_, *z_, *h_, *dz_, *y_, *dy_, *dw0_, *dw1_, *dlnA_, *gnA_, *h2_, *y2_;
    cudaGetSymbolAddress((void**)&k_,    g_k);
    cudaGetSymbolAddress((void**)&v_,    g_v);
    cudaGetSymbolAddress((void**)&q_,    g_q);
    cudaGetSymbolAddress((void**)&qr_,   g_qr);
    cudaGetSymbolAddress((void**)&xr_,   g_xr);
    cudaGetSymbolAddress((void**)&wkr_,  g_wkr);
    cudaGetSymbolAddress((void**)&wvr_,  g_wvr);
    cudaGetSymbolAddress((void**)&wqr_,  g_wqr);
    cudaGetSymbolAddress((void**)&w0r_,  g_w0r);
    cudaGetSymbolAddress((void**)&w1r_,  g_w1r);
    cudaGetSymbolAddress((void**)&kallr_,g_kallr);
    cudaGetSymbolAddress((void**)&z_,    g_z);
    cudaGetSymbolAddress((void**)&h_,    g_h);
    cudaGetSymbolAddress((void**)&dz_,   g_dz);
    cudaGetSymbolAddress((void**)&y_,    g_y);
    cudaGetSymbolAddress((void**)&dy_,   g_dy);
    cudaGetSymbolAddress((void**)&dw0_,  g_dw0);
    cudaGetSymbolAddress((void**)&dw1_,  g_dw1);
    cudaGetSymbolAddress((void**)&dlnA_, g_dlnA);
    cudaGetSymbolAddress((void**)&gnA_,  g_gnormA);
    cudaGetSymbolAddress((void**)&h2_,   g_h2);
    cudaGetSymbolAddress((void**)&y2_,   g_y2);

    // template instantiations + dynamic smem sizes
    auto G1 = gemm_tc<128,256,64,64,8,true,true>;   // big parallel NT
    auto Gz = gemm_tc<64,128,32,64,4,true,true>;    // z = kc @ w0^T
    auto Gy = gemm_tc<64,64,32,32,4,true,true>;     // y = h @ w1^T
    auto Gw = gemm_tc<128,128,64,64,4,false,false>; // TN weight grads
    const int S1 = 2 * (128*36 + 256*36) * 4;       // 110592
    const int Sz = 2 * (64*36 + 128*36) * 4;        // 55296
    const int Sy = 2 * (64*36 + 64*36) * 4;         // 36864
    const int Sw = 2 * (32*136 + 32*136) * 4;       // 69632
    const int Sf = Sw;                              // fused max
    static int attr_done = 0;
    if (!attr_done) {
        cudaFuncSetAttribute(G1, cudaFuncAttributeMaxDynamicSharedMemorySize, S1);
        cudaFuncSetAttribute(Gz, cudaFuncAttributeMaxDynamicSharedMemorySize, Sz);
        cudaFuncSetAttribute(Gy, cudaFuncAttributeMaxDynamicSharedMemorySize, Sy);
        cudaFuncSetAttribute(Gw, cudaFuncAttributeMaxDynamicSharedMemorySize, Sw);
        cudaFuncSetAttribute(fused_dz_dw1, cudaFuncAttributeMaxDynamicSharedMemorySize, Sf);
        attr_done = 1;
    }

    // ---- init + pre-round inputs ----
    init_mem<<<2048, 256>>>(mw0, mw1, mln);
    round_copy<<<2048, 256>>>(xr_, x, NROWS * HH / 4);
    round_copy<<<512, 256>>>(wkr_, wk, HH * HH / 4);
    round_copy<<<512, 256>>>(wvr_, wv, HH * HH / 4);
    round_copy<<<512, 256>>>(wqr_, wq, HH * HH / 4);

    // ---- precompute k, v, q ----
    dim3 gKVQ(HH / 256, NROWS / 128);
    G1<<<gKVQ, 256, S1>>>(xr_, wkr_, k_, nullptr, nullptr, NROWS, HH, HH, EPI_SILU);
    rmsnorm_rows<<<NROWS, 256>>>(k_, kn, nullptr);
    G1<<<gKVQ, 256, S1>>>(xr_, wvr_, v_, nullptr, nullptr, NROWS, HH, HH, EPI_SILU);
    G1<<<gKVQ, 256, S1>>>(xr_, wqr_, q_, nullptr, nullptr, NROWS, HH, HH, EPI_SILU);
    rmsnorm_rows<<<NROWS, 256>>>(q_, qn, qr_);
    gather_all<<<2048, 256>>>();

    // ---- adaptive coefficients ----
    coeff_dot<<<BB * NCH, 256>>>(x, aw, tw, ew);
    coeff_finalize<<<1, 256>>>();

    // ---- sequential scan over chunks ----
    for (int c = 0; c < NCH; c++) {
        const float* kcr = kallr_ + (size_t)c * NN * HH;
        // z = kc @ w0^T ; h = round(silu(z)), aux z full
        Gz<<<dim3(II / 128, NN / 64), 128, Sz>>>(kcr, w0r_, h_, z_, nullptr, NN, II, HH, EPI_SILU_AUX_R);
        // y = h @ w1^T
        Gy<<<dim3(HH / 64, NN / 64), 128, Sy>>>(h_, w1r_, y_, nullptr, nullptr, NN, HH, II, EPI_NONE);
        // backward through residual + rmsnorm + MSE (dln atomics)
        chunk_bwd_y<<<NN, 256>>>(c);
        // dz = (dy @ w1) * silu'(z)  ||  dw1 = dy^T @ h (+grad sumsq), one launch
        fused_dz_dw1<<<dim3(16, 8, 2), 128, Sf>>>(dy_, w1r_, dz_, z_, h_, dw1_, gnA_ + c);
        // d_w0 = d_z^T @ kc (TN, fused grad sumsq + dln^2)
        Gw<<<dim3(HH / 128, II / 128), 128, Sw>>>(dz_, kcr, dw0_, dlnA_ + c * HH, gnA_ + c, II, HH, NN, EPI_GRAD_LN);
        // clipped EMA update (+ rounded weight copies)
        update_params<<<1024, 256>>>(c);
    }

    // ---- retrieval with final memory ----
    G1<<<dim3(II / 256, NROWS / 128), 256, S1>>>(qr_, w0r_, h2_, nullptr, nullptr, NROWS, II, HH, EPI_SILU_R);
    G1<<<dim3(HH / 256, NROWS / 128), 256, S1>>>(h2_, w1r_, y2_, nullptr, nullptr, NROWS, HH, II, EPI_NONE);
    final_out<<<NROWS, 256>>>(out);
}

// round 8
// speedup vs baseline: 2.8080x; 1.1040x over previous
#include <cuda_runtime.h>
#include <math.h>
#include <stdint.h>

#define BB 8
#define SS 2048
#define HH 1024
#define CC 64
#define NCH 32
#define NN 512      /* BB*CC rows per chunk */
#define II 2048     /* INTER */
#define NROWS 16384 /* BB*SS */

#define EPI_NONE 0
#define EPI_SILU 1
#define EPI_SILU_AUX 2
#define EPI_DSILU 3
#define EPI_GRAD 4
#define EPI_GRAD_LN 5

// ---------------- device scratch (no allocation allowed) ----------------
__device__ __align__(16) float g_k[NROWS * HH];
__device__ __align__(16) float g_v[NROWS * HH];
__device__ __align__(16) float g_q[NROWS * HH];
__device__ __align__(16) float g_kall[NROWS * HH];
__device__ __align__(16) float g_vall[NROWS * HH];
__device__ __align__(16) float g_w0[II * HH];
__device__ __align__(16) float g_w1[HH * II];
__device__ __align__(16) float g_ln[HH];
__device__ __align__(16) float g_s0[II * HH];
__device__ __align__(16) float g_s1[HH * II];
__device__ __align__(16) float g_sln[HH];
__device__ __align__(16) float g_z[NN * II];
__device__ __align__(16) float g_h[NN * II];
__device__ __align__(16) float g_dz[NN * II];
__device__ __align__(16) float g_y[2 * NN * HH];   /* two split-K partials */
__device__ __align__(16) float g_dy[NN * HH];
__device__ __align__(16) float g_dw0[II * HH];
__device__ __align__(16) float g_dw1[HH * II];
__device__ __align__(16) float g_dlnA[NCH * HH];
__device__ __align__(16) float g_gnormA[NCH];
__device__ __align__(16) float g_h2[NROWS * II];
__device__ __align__(16) float g_y2[NROWS * HH];
__device__ __align__(16) float g_dotA[BB * NCH];
__device__ __align__(16) float g_dotT[BB * NCH];
__device__ __align__(16) float g_dotE[BB * NCH];
__device__ __align__(16) float g_beta[NCH];
__device__ __align__(16) float g_eta[NCH];
__device__ __align__(16) float g_theta[BB * NCH];

// ---------------- helpers ----------------
__device__ __forceinline__ float sigm(float x) { return 1.f / (1.f + expf(-x)); }
__device__ __forceinline__ float silu_f(float x) { return x / (1.f + expf(-x)); }
__device__ __forceinline__ float dsilu_f(float x) {
    float s = 1.f / (1.f + expf(-x));
    return s * (1.f + x * (1.f - s));
}

__device__ __forceinline__ void mma8(float* d, const uint32_t* a, const uint32_t* b) {
    asm volatile(
        "mma.sync.aligned.m16n8k8.row.col.f32.tf32.tf32.f32 "
        "{%0,%1,%2,%3}, {%4,%5,%6,%7}, {%8,%9}, {%0,%1,%2,%3};"
        : "+f"(d[0]), "+f"(d[1]), "+f"(d[2]), "+f"(d[3])
        : "r"(a[0]), "r"(a[1]), "r"(a[2]), "r"(a[3]), "r"(b[0]), "r"(b[1]));
}

__device__ __forceinline__ void cpa16(float* dst, const float* src) {
    uint32_t d = (uint32_t)__cvta_generic_to_shared(dst);
    asm volatile("cp.async.cg.shared.global [%0], [%1], 16;\n" :: "r"(d), "l"(src));
}
__device__ __forceinline__ void cpa_commit() { asm volatile("cp.async.commit_group;\n"); }

__device__ __forceinline__ float block_sum(float v) {
    __shared__ float sh[32];
    __shared__ float tot;
    int lane = threadIdx.x & 31;
    int w = threadIdx.x >> 5;
#pragma unroll
    for (int o = 16; o > 0; o >>= 1) v += __shfl_xor_sync(0xffffffffu, v, o);
    if (lane == 0) sh[w] = v;
    __syncthreads();
    if (w == 0) {
        float r = (lane < (blockDim.x >> 5)) ? sh[lane] : 0.f;
#pragma unroll
        for (int o = 16; o > 0; o >>= 1) r += __shfl_xor_sync(0xffffffffu, r, o);
        if (lane == 0) tot = r;
    }
    __syncthreads();
    return tot;
}

// ---------------- tf32 tensor-core GEMM body (cp.async double-buffered) --------
// C[M,N] = opA(A) * opB(B).  Raw fp32 inputs; MMA truncates to tf32 (RZ).
//   AT=true : A is M x K row-major (row stride lda)
//   AT=false: A is K x M row-major (=A^T, row stride lda)
//   BT=true : B is N x K row-major (row stride ldb)
//   BT=false: B is K x N row-major (row stride ldb)
template<int BM, int BN, int WM, int WN, int NWARP, bool AT, bool BT>
__device__ __forceinline__ void gemm_body(
    float* sm,
    const float* __restrict__ A, const float* __restrict__ B,
    float* __restrict__ C, float* __restrict__ aux, float* __restrict__ gn,
    int M, int N, int K, int lda, int ldb, int epi, int bx, int by)
{
    constexpr int NT = NWARP * 32;
    constexpr int SA = BM + 8;
    constexpr int SB = BN + 8;
    constexpr int ASZ = AT ? BM * 36 : 32 * SA;
    constexpr int BSZ = BT ? BN * 36 : 32 * SB;
    constexpr int PA = AT ? (BM * 8) / NT : (32 * (BM / 4)) / NT;
    constexpr int PB = BT ? (BN * 8) / NT : (32 * (BN / 4)) / NT;
    constexpr int WGM = BM / WM;
    constexpr int MI = WM / 16, NI = WN / 8;

    float* Ab[2] = { sm, sm + ASZ };
    float* Bb[2] = { sm + 2 * ASZ, sm + 2 * ASZ + BSZ };

    const int t = threadIdx.x;
    const int bm = by * BM, bn = bx * BN;
    const int wid = t >> 5, lane = t & 31;
    const int wm = (wid % WGM) * WM;
    const int wn = (wid / WGM) * WN;
    const int gp = lane >> 2, kq = lane & 3;

    float acc[MI][NI][4];
#pragma unroll
    for (int i = 0; i < MI; i++)
#pragma unroll
        for (int j = 0; j < NI; j++)
#pragma unroll
            for (int q = 0; q < 4; q++) acc[i][j][q] = 0.f;

    auto issue = [&](int k0, int buf) {
        float* As = Ab[buf];
        float* Bs = Bb[buf];
#pragma unroll
        for (int p = 0; p < PA; p++) {
            int idx = p * NT + t;
            if constexpr (AT) {
                int row = idx >> 3, seg = idx & 7;
                cpa16(As + row * 36 + seg * 4, A + (size_t)(bm + row) * lda + k0 + seg * 4);
            } else {
                int kk = idx / (BM / 4), mseg = idx % (BM / 4);
                cpa16(As + kk * SA + mseg * 4, A + (size_t)(k0 + kk) * lda + bm + mseg * 4);
            }
        }
#pragma unroll
        for (int p = 0; p < PB; p++) {
            int idx = p * NT + t;
            if constexpr (BT) {
                int row = idx >> 3, seg = idx & 7;
                cpa16(Bs + row * 36 + seg * 4, B + (size_t)(bn + row) * ldb + k0 + seg * 4);
            } else {
                int kk = idx / (BN / 4), nseg = idx % (BN / 4);
                cpa16(Bs + kk * SB + nseg * 4, B + (size_t)(k0 + kk) * ldb + bn + nseg * 4);
            }
        }
        cpa_commit();
    };

    issue(0, 0);
    const int nit = K / 32;
    for (int it = 0; it < nit; it++) {
        if (it + 1 < nit) {
            issue((it + 1) * 32, (it + 1) & 1);
            asm volatile("cp.async.wait_group 1;\n");
        } else {
            asm volatile("cp.async.wait_group 0;\n");
        }
        __syncthreads();
        const float* As = Ab[it & 1];
        const float* Bs = Bb[it & 1];
#pragma unroll
        for (int ks = 0; ks < 4; ks++) {
            const int k8 = ks * 8 + kq;
            uint32_t af[MI][4], bf[NI][2];
#pragma unroll
            for (int mi = 0; mi < MI; mi++) {
                int r0 = wm + mi * 16 + gp;
                if constexpr (AT) {
                    af[mi][0] = __float_as_uint(As[r0 * 36 + k8]);
                    af[mi][1] = __float_as_uint(As[(r0 + 8) * 36 + k8]);
                    af[mi][2] = __float_as_uint(As[r0 * 36 + k8 + 4]);
                    af[mi][3] = __float_as_uint(As[(r0 + 8) * 36 + k8 + 4]);
                } else {
                    af[mi][0] = __float_as_uint(As[k8 * SA + r0]);
                    af[mi][1] = __float_as_uint(As[k8 * SA + r0 + 8]);
                    af[mi][2] = __float_as_uint(As[(k8 + 4) * SA + r0]);
                    af[mi][3] = __float_as_uint(As[(k8 + 4) * SA + r0 + 8]);
                }
            }
#pragma unroll
            for (int ni = 0; ni < NI; ni++) {
                int c0 = wn + ni * 8 + gp;
                if constexpr (BT) {
                    bf[ni][0] = __float_as_uint(Bs[c0 * 36 + k8]);
                    bf[ni][1] = __float_as_uint(Bs[c0 * 36 + k8 + 4]);
                } else {
                    bf[ni][0] = __float_as_uint(Bs[k8 * SB + c0]);
                    bf[ni][1] = __float_as_uint(Bs[(k8 + 4) * SB + c0]);
                }
            }
#pragma unroll
            for (int mi = 0; mi < MI; mi++)
#pragma unroll
                for (int ni = 0; ni < NI; ni++)
                    mma8(acc[mi][ni], af[mi], bf[ni]);
        }
        __syncthreads();
    }

    // epilogue
    float gs = 0.f;
#pragma unroll
    for (int mi = 0; mi < MI; mi++) {
#pragma unroll
        for (int ni = 0; ni < NI; ni++) {
            int r0 = bm + wm + mi * 16 + gp;
            int c = bn + wn + ni * 8 + kq * 2;
            size_t o0 = (size_t)r0 * N + c;
            size_t o1 = (size_t)(r0 + 8) * N + c;
            float2 v0 = make_float2(acc[mi][ni][0], acc[mi][ni][1]);
            float2 v1 = make_float2(acc[mi][ni][2], acc[mi][ni][3]);
            if (epi == EPI_SILU) {
                v0.x = silu_f(v0.x); v0.y = silu_f(v0.y);
                v1.x = silu_f(v1.x); v1.y = silu_f(v1.y);
            } else if (epi == EPI_SILU_AUX) {
                *(float2*)(aux + o0) = v0;
                *(float2*)(aux + o1) = v1;
                v0.x = silu_f(v0.x); v0.y = silu_f(v0.y);
                v1.x = silu_f(v1.x); v1.y = silu_f(v1.y);
            } else if (epi == EPI_DSILU) {
                float2 z0 = *(const float2*)(aux + o0);
                float2 z1 = *(const float2*)(aux + o1);
                v0.x *= dsilu_f(z0.x); v0.y *= dsilu_f(z0.y);
                v1.x *= dsilu_f(z1.x); v1.y *= dsilu_f(z1.y);
            } else if (epi >= EPI_GRAD) {
                gs += v0.x * v0.x + v0.y * v0.y + v1.x * v1.x + v1.y * v1.y;
            }
            *(float2*)(C + o0) = v0;
            *(float2*)(C + o1) = v1;
        }
    }
    if (epi >= EPI_GRAD) {
        gs = block_sum(gs);
        if (t == 0) atomicAdd(gn, gs);
        if (epi == EPI_GRAD_LN && bx == 0 && by == 0) {
            float s = 0.f;
            for (int i = t; i < HH; i += NT) { float d = aux[i]; s += d * d; }
            s = block_sum(s);
            if (t == 0) atomicAdd(gn, s);
        }
    }
}

template<int BM, int BN, int WM, int WN, int NWARP, bool AT, bool BT>
__global__ __launch_bounds__(NWARP * 32) void gemm_tc(
    const float* __restrict__ A, const float* __restrict__ B,
    float* __restrict__ C, float* __restrict__ aux, float* __restrict__ gn,
    int M, int N, int K, int lda, int ldb, int epi)
{
    extern __shared__ float sm[];
    gemm_body<BM, BN, WM, WN, NWARP, AT, BT>(sm, A, B, C, aux, gn, M, N, K, lda, ldb,
                                             epi, blockIdx.x, blockIdx.y);
}

// split-K y GEMM: y_part[z][NN,HH] = h[:, z*1024 : z*1024+1024] @ w1[:, same]^T
__global__ __launch_bounds__(128) void gemm_y_sk(
    const float* __restrict__ h, const float* __restrict__ w1, float* __restrict__ yp)
{
    extern __shared__ float sm[];
    int z = blockIdx.z;
    gemm_body<64, 128, 32, 64, 4, true, true>(
        sm, h + z * (II / 2), w1 + z * (II / 2), yp + (size_t)z * NN * HH,
        nullptr, nullptr, NN, HH, II / 2, II, II, EPI_NONE, blockIdx.x, blockIdx.y);
}

// fused: blockIdx.z==0 -> dz = (dy @ w1) * silu'(z)    [64x128 tiles, grid 16x8]
//        blockIdx.z==1 -> dw1 = dy^T @ h + grad sumsq   [128x128 tiles, grid 16x8]
__global__ __launch_bounds__(128) void fused_dz_dw1(
    const float* __restrict__ dy, const float* __restrict__ w1,
    float* __restrict__ dz, float* __restrict__ z,
    const float* __restrict__ h, float* __restrict__ dw1, float* __restrict__ gn)
{
    extern __shared__ float sm[];
    if (blockIdx.z == 0)
        gemm_body<64, 128, 32, 64, 4, true, false>(sm, dy, w1, dz, z, nullptr,
                                                   NN, II, HH, HH, II, EPI_DSILU,
                                                   blockIdx.x, blockIdx.y);
    else
        gemm_body<128, 128, 64, 64, 4, false, false>(sm, dy, h, dw1, nullptr, gn,
                                                     HH, II, NN, HH, II, EPI_GRAD,
                                                     blockIdx.x, blockIdx.y);
}

// ---------------- elementwise / reduction kernels ----------------
__global__ __launch_bounds__(256) void init_mem(
    const float* __restrict__ w0, const float* __restrict__ w1, const float* __restrict__ ln)
{
    int n = II * HH;
    for (int i = blockIdx.x * blockDim.x + threadIdx.x; i < n; i += gridDim.x * blockDim.x) {
        g_w0[i] = w0[i]; g_s0[i] = 0.f;
        g_w1[i] = w1[i]; g_s1[i] = 0.f;
        if (i < HH) { g_ln[i] = ln[i]; g_sln[i] = 0.f; }
        if (i < NCH * HH) g_dlnA[i] = 0.f;
        if (i < NCH) g_gnormA[i] = 0.f;
    }
}

__global__ __launch_bounds__(256) void rmsnorm_rows(float* __restrict__ buf, const float* __restrict__ w) {
    int r = blockIdx.x;
    int t = threadIdx.x;
    float4* row = (float4*)(buf + (size_t)r * HH);
    float4 v = row[t];
    float ss = v.x * v.x + v.y * v.y + v.z * v.z + v.w * v.w;
    ss = block_sum(ss);
    float rs = rsqrtf(ss / HH + 1e-6f);
    float4 wv = ((const float4*)w)[t];
    v.x *= rs * wv.x; v.y *= rs * wv.y; v.z *= rs * wv.z; v.w *= rs * wv.w;
    row[t] = v;
}

// gather all chunks once
__global__ __launch_bounds__(256) void gather_all() {
    const int H4 = HH / 4;
    const int per = NN * H4;
    int ntot = NCH * per;
    for (int i = blockIdx.x * blockDim.x + threadIdx.x; i < ntot; i += gridDim.x * blockDim.x) {
        int c = i / per, rem = i - c * per;
        int m = rem / H4, q = rem - m * H4;
        int src = ((m >> 6) * SS + c * CC + (m & 63)) * H4 + q;
        ((float4*)g_kall)[i] = ((const float4*)g_k)[src];
        ((float4*)g_vall)[i] = ((const float4*)g_v)[src];
    }
}

__global__ __launch_bounds__(256) void coeff_dot(
    const float* __restrict__ x, const float* __restrict__ aw,
    const float* __restrict__ tw, const float* __restrict__ ew)
{
    int bc = blockIdx.x;
    int b = bc >> 5, nc = bc & 31;
    const float4* xf = (const float4*)(x + (size_t)(b * SS + nc * CC) * HH);
    const float4* a4 = (const float4*)aw;
    const float4* t4 = (const float4*)tw;
    const float4* e4 = (const float4*)ew;
    const int L4 = CC * HH / 4;
    float sa = 0.f, st = 0.f, se = 0.f;
    for (int i = threadIdx.x; i < L4; i += blockDim.x) {
        float4 xv = xf[i];
        float4 av = a4[i]; sa += xv.x * av.x + xv.y * av.y + xv.z * av.z + xv.w * av.w;
        float4 tv = t4[i]; st += xv.x * tv.x + xv.y * tv.y + xv.z * tv.z + xv.w * tv.w;
        float4 ev = e4[i]; se += xv.x * ev.x + xv.y * ev.y + xv.z * ev.z + xv.w * ev.w;
    }
    sa = block_sum(sa);
    st = block_sum(st);
    se = block_sum(se);
    if (threadIdx.x == 0) { g_dotA[bc] = sa; g_dotT[bc] = st; g_dotE[bc] = se; }
}

__global__ void coeff_finalize() {
    int t = threadIdx.x;
    if (t < BB * NCH) g_theta[t] = sigm(g_dotT[t]) * 0.01f;
    if (t < NCH) {
        float sa = 0.f, se = 0.f;
        for (int b = 0; b < BB; b++) { sa += g_dotA[b * NCH + t]; se += g_dotE[b * NCH + t]; }
        float al = sigm(sa / (float)BB);
        g_beta[t] = 1.f - al;
        g_eta[t] = sigm(se / (float)BB);
    }
}

// backward through rmsnorm + residual + weighted MSE; combines split-K y parts
__global__ __launch_bounds__(256) void chunk_bwd_y(int c) {
    int r = blockIdx.x;
    int t = threadIdx.x;
    int b = r >> 6;
    const float* kc = g_kall + (size_t)c * NN * HH;
    const float* vc = g_vall + (size_t)c * NN * HH;
    float4 ya = ((const float4*)(g_y + (size_t)r * HH))[t];
    float4 yb = ((const float4*)(g_y + (size_t)(NN + r) * HH))[t];
    float4 y4;
    y4.x = ya.x + yb.x; y4.y = ya.y + yb.y; y4.z = ya.z + yb.z; y4.w = ya.w + yb.w;
    float ss = y4.x * y4.x + y4.y * y4.y + y4.z * y4.z + y4.w * y4.w;
    ss = block_sum(ss);
    float rs = rsqrtf(ss / HH + 1e-6f);
    float th = g_theta[b * NCH + c];
    float scale = 2.f * th / ((float)NN * (float)HH);
    float4 k4 = ((const float4*)(kc + (size_t)r * HH))[t];
    float4 v4 = ((const float4*)(vc + (size_t)r * HH))[t];
    float4 l4 = ((const float4*)g_ln)[t];
    float4 gg;
    gg.x = scale * (k4.x + y4.x * rs * l4.x - v4.x);
    gg.y = scale * (k4.y + y4.y * rs * l4.y - v4.y);
    gg.z = scale * (k4.z + y4.z * rs * l4.z - v4.z);
    gg.w = scale * (k4.w + y4.w * rs * l4.w - v4.w);
    float sv = gg.x * l4.x * y4.x + gg.y * l4.y * y4.y + gg.z * l4.z * y4.z + gg.w * l4.w * y4.w;
    sv = block_sum(sv);
    float c3 = rs * rs * rs * sv / (float)HH;
    float4 dy;
    dy.x = rs * gg.x * l4.x - c3 * y4.x;
    dy.y = rs * gg.y * l4.y - c3 * y4.y;
    dy.z = rs * gg.z * l4.z - c3 * y4.z;
    dy.w = rs * gg.w * l4.w - c3 * y4.w;
    ((float4*)(g_dy + (size_t)r * HH))[t] = dy;
    float* dln = g_dlnA + c * HH;
    atomicAdd(&dln[t * 4 + 0], gg.x * y4.x * rs);
    atomicAdd(&dln[t * 4 + 1], gg.y * y4.y * rs);
    atomicAdd(&dln[t * 4 + 2], gg.z * y4.z * rs);
    atomicAdd(&dln[t * 4 + 3], gg.w * y4.w * rs);
}

__global__ __launch_bounds__(256) void update_params(int c) {
    float total = sqrtf(g_gnormA[c]);
    float clip = fminf(1.0f / (total + 1e-6f), 1.0f);
    float eta = g_eta[c], beta = g_beta[c];
    const float* dln = g_dlnA + c * HH;
    const int n0 = II * HH, n1 = 2 * II * HH, nt = 2 * II * HH + HH;
    for (int i = blockIdx.x * blockDim.x + threadIdx.x; i < nt; i += gridDim.x * blockDim.x) {
        if (i < n0) {
            float ns = eta * g_s0[i] - g_dw0[i] * clip;
            g_s0[i] = ns;
            g_w0[i] = beta * g_w0[i] + ns;
        } else if (i < n1) {
            int j = i - n0;
            float ns = eta * g_s1[j] - g_dw1[j] * clip;
            g_s1[j] = ns;
            g_w1[j] = beta * g_w1[j] + ns;
        } else {
            int j = i - n1;
            float ns = eta * g_sln[j] - dln[j] * clip;
            g_sln[j] = ns;
            g_ln[j] = beta * g_ln[j] + ns;
        }
    }
}

__global__ __launch_bounds__(256) void final_out(float* __restrict__ out) {
    int r = blockIdx.x, t = threadIdx.x;
    float4 y4 = ((const float4*)(g_y2 + (size_t)r * HH))[t];
    float ss = y4.x * y4.x + y4.y * y4.y + y4.z * y4.z + y4.w * y4.w;
    ss = block_sum(ss);
    float rs = rsqrtf(ss / HH + 1e-6f);
    float4 q4 = ((const float4*)(g_q + (size_t)r * HH))[t];
    float4 l4 = ((const float4*)g_ln)[t];
    float4 o;
    o.x = q4.x + y4.x * rs * l4.x;
    o.y = q4.y + y4.y * rs * l4.y;
    o.z = q4.z + y4.z * rs * l4.z;
    o.w = q4.w + y4.w * rs * l4.w;
    ((float4*)(out + (size_t)r * HH))[t] = o;
}

// ---------------- host launcher ----------------
extern "C" void kernel_launch(void* const* d_in, const int* in_sizes, int n_in,
                              void* d_out, int out_size) {
    const float* x   = (const float*)d_in[0];
    const float* wq  = (const float*)d_in[1];
    const float* wk  = (const float*)d_in[2];
    const float* wv  = (const float*)d_in[3];
    const float* qn  = (const float*)d_in[4];
    const float* kn  = (const float*)d_in[5];
    const float* aw  = (const float*)d_in[6];
    const float* tw  = (const float*)d_in[7];
    const float* ew  = (const float*)d_in[8];
    const float* mw0 = (const float*)d_in[9];
    const float* mw1 = (const float*)d_in[10];
    const float* mln = (const float*)d_in[11];
    float* out = (float*)d_out;

    float *k_, *v_, *q_, *w0_, *w1_, *kall_, *z_, *h_, *dz_, *y_, *dy_;
    float *dw0_, *dw1_, *dlnA_, *gnA_, *h2_, *y2_;
    cudaGetSymbolAddress((void**)&k_,    g_k);
    cudaGetSymbolAddress((void**)&v_,    g_v);
    cudaGetSymbolAddress((void**)&q_,    g_q);
    cudaGetSymbolAddress((void**)&w0_,   g_w0);
    cudaGetSymbolAddress((void**)&w1_,   g_w1);
    cudaGetSymbolAddress((void**)&kall_, g_kall);
    cudaGetSymbolAddress((void**)&z_,    g_z);
    cudaGetSymbolAddress((void**)&h_,    g_h);
    cudaGetSymbolAddress((void**)&dz_,   g_dz);
    cudaGetSymbolAddress((void**)&y_,    g_y);
    cudaGetSymbolAddress((void**)&dy_,   g_dy);
    cudaGetSymbolAddress((void**)&dw0_,  g_dw0);
    cudaGetSymbolAddress((void**)&dw1_,  g_dw1);
    cudaGetSymbolAddress((void**)&dlnA_, g_dlnA);
    cudaGetSymbolAddress((void**)&gnA_,  g_gnormA);
    cudaGetSymbolAddress((void**)&h2_,   g_h2);
    cudaGetSymbolAddress((void**)&y2_,   g_y2);

    // template instantiations + dynamic smem sizes
    auto G1 = gemm_tc<128,256,64,64,8,true,true>;   // big parallel NT
    auto Gz = gemm_tc<64,128,32,64,4,true,true>;    // z = kc @ w0^T
    auto Gw = gemm_tc<128,128,64,64,4,false,false>; // TN dw0
    const int S1 = 2 * (128*36 + 256*36) * 4;       // 110592
    const int Sz = 2 * (64*36 + 128*36) * 4;        // 55296
    const int Sy = Sz;                              // gemm_y_sk same tile
    const int Sw = 2 * (32*136 + 32*136) * 4;       // 69632
    const int Sf = Sw;                              // fused max
    static int attr_done = 0;
    if (!attr_done) {
        cudaFuncSetAttribute(G1, cudaFuncAttributeMaxDynamicSharedMemorySize, S1);
        cudaFuncSetAttribute(Gz, cudaFuncAttributeMaxDynamicSharedMemorySize, Sz);
        cudaFuncSetAttribute(gemm_y_sk, cudaFuncAttributeMaxDynamicSharedMemorySize, Sy);
        cudaFuncSetAttribute(Gw, cudaFuncAttributeMaxDynamicSharedMemorySize, Sw);
        cudaFuncSetAttribute(fused_dz_dw1, cudaFuncAttributeMaxDynamicSharedMemorySize, Sf);
        attr_done = 1;
    }

    // ---- init memory params ----
    init_mem<<<2048, 256>>>(mw0, mw1, mln);

    // ---- precompute k, v, q (raw fp32 inputs; MMA truncates to tf32) ----
    dim3 gKVQ(HH / 256, NROWS / 128);
    G1<<<gKVQ, 256, S1>>>(x, wk, k_, nullptr, nullptr, NROWS, HH, HH, HH, HH, EPI_SILU);
    rmsnorm_rows<<<NROWS, 256>>>(k_, kn);
    G1<<<gKVQ, 256, S1>>>(x, wv, v_, nullptr, nullptr, NROWS, HH, HH, HH, HH, EPI_SILU);
    G1<<<gKVQ, 256, S1>>>(x, wq, q_, nullptr, nullptr, NROWS, HH, HH, HH, HH, EPI_SILU);
    rmsnorm_rows<<<NROWS, 256>>>(q_, qn);
    gather_all<<<2048, 256>>>();

    // ---- adaptive coefficients ----
    coeff_dot<<<BB * NCH, 256>>>(x, aw, tw, ew);
    coeff_finalize<<<1, 256>>>();

    // ---- sequential scan over chunks ----
    for (int c = 0; c < NCH; c++) {
        const float* kc = kall_ + (size_t)c * NN * HH;
        // z = kc @ w0^T ; h = silu(z), aux z
        Gz<<<dim3(II / 128, NN / 64), 128, Sz>>>(kc, w0_, h_, z_, nullptr, NN, II, HH, HH, HH, EPI_SILU_AUX);
        // y = h @ w1^T, split-K=2 into two partial buffers (combined in chunk_bwd_y)
        gemm_y_sk<<<dim3(HH / 128, NN / 64, 2), 128, Sy>>>(h_, w1_, y_);
        // backward through residual + rmsnorm + MSE (dln atomics)
        chunk_bwd_y<<<NN, 256>>>(c);
        // dz = (dy @ w1) * silu'(z)  ||  dw1 = dy^T @ h (+grad sumsq), one launch
        fused_dz_dw1<<<dim3(16, 8, 2), 128, Sf>>>(dy_, w1_, dz_, z_, h_, dw1_, gnA_ + c);
        // d_w0 = d_z^T @ kc (TN, fused grad sumsq + dln^2)
        Gw<<<dim3(HH / 128, II / 128), 128, Sw>>>(dz_, kc, dw0_, dlnA_ + c * HH, gnA_ + c, II, HH, NN, II, HH, EPI_GRAD_LN);
        // clipped EMA update
        update_params<<<1024, 256>>>(c);
    }

    // ---- retrieval with final memory ----
    G1<<<dim3(II / 256, NROWS / 128), 256, S1>>>(q_, w0_, h2_, nullptr, nullptr, NROWS, II, HH, HH, HH, EPI_SILU);
    G1<<<dim3(HH / 256, NROWS / 128), 256, S1>>>(h2_, w1_, y2_, nullptr, nullptr, NROWS, HH, II, II, II, EPI_NONE);
    final_out<<<NROWS, 256>>>(out);
}

// round 9
// speedup vs baseline: 2.9268x; 1.0423x over previous
#include <cuda_runtime.h>
#include <math.h>
#include <stdint.h>

#define BB 8
#define SS 2048
#define HH 1024
#define CC 64
#define NCH 32
#define NN 512      /* BB*CC rows per chunk */
#define II 2048     /* INTER */
#define NROWS 16384 /* BB*SS */

#define EPI_NONE 0
#define EPI_SILU 1
#define EPI_SILU_AUX 2
#define EPI_DSILU 3
#define EPI_GRAD 4
#define EPI_GRAD_LN 5

// ---------------- device scratch (no allocation allowed) ----------------
__device__ __align__(16) float g_k[NROWS * HH];
__device__ __align__(16) float g_v[NROWS * HH];
__device__ __align__(16) float g_q[NROWS * HH];
__device__ __align__(16) float g_kall[NROWS * HH];
__device__ __align__(16) float g_vall[NROWS * HH];
__device__ __align__(16) float g_w0[II * HH];
__device__ __align__(16) float g_w1[HH * II];
__device__ __align__(16) float g_ln[HH];
__device__ __align__(16) float g_s0[II * HH];
__device__ __align__(16) float g_s1[HH * II];
__device__ __align__(16) float g_sln[HH];
__device__ __align__(16) float g_z[NN * II];
__device__ __align__(16) float g_zp[2 * NN * II];   /* z split-K partials */
__device__ __align__(16) float g_h[NN * II];
__device__ __align__(16) float g_dz[NN * II];
__device__ __align__(16) float g_dzp[2 * NN * II];  /* dz split-K partials */
__device__ __align__(16) float g_y[4 * NN * HH];    /* y split-K partials */
__device__ __align__(16) float g_dy[NN * HH];
__device__ __align__(16) float g_dw0[II * HH];
__device__ __align__(16) float g_dw1[HH * II];
__device__ __align__(16) float g_dlnA[NCH * HH];
__device__ __align__(16) float g_gnormA[NCH];
__device__ __align__(16) float g_h2[NROWS * II];
__device__ __align__(16) float g_y2[NROWS * HH];
__device__ __align__(16) float g_dotA[BB * NCH];
__device__ __align__(16) float g_dotT[BB * NCH];
__device__ __align__(16) float g_dotE[BB * NCH];
__device__ __align__(16) float g_beta[NCH];
__device__ __align__(16) float g_eta[NCH];
__device__ __align__(16) float g_theta[BB * NCH];

// ---------------- helpers ----------------
__device__ __forceinline__ float sigm(float x) { return 1.f / (1.f + expf(-x)); }
__device__ __forceinline__ float silu_f(float x) { return x / (1.f + expf(-x)); }
__device__ __forceinline__ float dsilu_f(float x) {
    float s = 1.f / (1.f + expf(-x));
    return s * (1.f + x * (1.f - s));
}

__device__ __forceinline__ void mma8(float* d, const uint32_t* a, const uint32_t* b) {
    asm volatile(
        "mma.sync.aligned.m16n8k8.row.col.f32.tf32.tf32.f32 "
        "{%0,%1,%2,%3}, {%4,%5,%6,%7}, {%8,%9}, {%0,%1,%2,%3};"
        : "+f"(d[0]), "+f"(d[1]), "+f"(d[2]), "+f"(d[3])
        : "r"(a[0]), "r"(a[1]), "r"(a[2]), "r"(a[3]), "r"(b[0]), "r"(b[1]));
}

__device__ __forceinline__ void cpa16(float* dst, const float* src) {
    uint32_t d = (uint32_t)__cvta_generic_to_shared(dst);
    asm volatile("cp.async.cg.shared.global [%0], [%1], 16;\n" :: "r"(d), "l"(src));
}
__device__ __forceinline__ void cpa_commit() { asm volatile("cp.async.commit_group;\n"); }

__device__ __forceinline__ float block_sum(float v) {
    __shared__ float sh[32];
    __shared__ float tot;
    int lane = threadIdx.x & 31;
    int w = threadIdx.x >> 5;
#pragma unroll
    for (int o = 16; o > 0; o >>= 1) v += __shfl_xor_sync(0xffffffffu, v, o);
    if (lane == 0) sh[w] = v;
    __syncthreads();
    if (w == 0) {
        float r = (lane < (blockDim.x >> 5)) ? sh[lane] : 0.f;
#pragma unroll
        for (int o = 16; o > 0; o >>= 1) r += __shfl_xor_sync(0xffffffffu, r, o);
        if (lane == 0) tot = r;
    }
    __syncthreads();
    return tot;
}

// ---------------- tf32 tensor-core GEMM body (cp.async double-buffered) --------
// C[M,N] = opA(A) * opB(B).  Raw fp32 inputs; MMA truncates to tf32 (RZ).
template<int BM, int BN, int WM, int WN, int NWARP, bool AT, bool BT>
__device__ __forceinline__ void gemm_body(
    float* sm,
    const float* __restrict__ A, const float* __restrict__ B,
    float* __restrict__ C, float* __restrict__ aux, float* __restrict__ gn,
    int M, int N, int K, int lda, int ldb, int epi, int bx, int by)
{
    constexpr int NT = NWARP * 32;
    constexpr int SA = BM + 8;
    constexpr int SB = BN + 8;
    constexpr int ASZ = AT ? BM * 36 : 32 * SA;
    constexpr int BSZ = BT ? BN * 36 : 32 * SB;
    constexpr int PA = AT ? (BM * 8) / NT : (32 * (BM / 4)) / NT;
    constexpr int PB = BT ? (BN * 8) / NT : (32 * (BN / 4)) / NT;
    constexpr int WGM = BM / WM;
    constexpr int MI = WM / 16, NI = WN / 8;

    float* Ab[2] = { sm, sm + ASZ };
    float* Bb[2] = { sm + 2 * ASZ, sm + 2 * ASZ + BSZ };

    const int t = threadIdx.x;
    const int bm = by * BM, bn = bx * BN;
    const int wid = t >> 5, lane = t & 31;
    const int wm = (wid % WGM) * WM;
    const int wn = (wid / WGM) * WN;
    const int gp = lane >> 2, kq = lane & 3;

    float acc[MI][NI][4];
#pragma unroll
    for (int i = 0; i < MI; i++)
#pragma unroll
        for (int j = 0; j < NI; j++)
#pragma unroll
            for (int q = 0; q < 4; q++) acc[i][j][q] = 0.f;

    auto issue = [&](int k0, int buf) {
        float* As = Ab[buf];
        float* Bs = Bb[buf];
#pragma unroll
        for (int p = 0; p < PA; p++) {
            int idx = p * NT + t;
            if constexpr (AT) {
                int row = idx >> 3, seg = idx & 7;
                cpa16(As + row * 36 + seg * 4, A + (size_t)(bm + row) * lda + k0 + seg * 4);
            } else {
                int kk = idx / (BM / 4), mseg = idx % (BM / 4);
                cpa16(As + kk * SA + mseg * 4, A + (size_t)(k0 + kk) * lda + bm + mseg * 4);
            }
        }
#pragma unroll
        for (int p = 0; p < PB; p++) {
            int idx = p * NT + t;
            if constexpr (BT) {
                int row = idx >> 3, seg = idx & 7;
                cpa16(Bs + row * 36 + seg * 4, B + (size_t)(bn + row) * ldb + k0 + seg * 4);
            } else {
                int kk = idx / (BN / 4), nseg = idx % (BN / 4);
                cpa16(Bs + kk * SB + nseg * 4, B + (size_t)(k0 + kk) * ldb + bn + nseg * 4);
            }
        }
        cpa_commit();
    };

    issue(0, 0);
    const int nit = K / 32;
    for (int it = 0; it < nit; it++) {
        if (it + 1 < nit) {
            issue((it + 1) * 32, (it + 1) & 1);
            asm volatile("cp.async.wait_group 1;\n");
        } else {
            asm volatile("cp.async.wait_group 0;\n");
        }
        __syncthreads();
        const float* As = Ab[it & 1];
        const float* Bs = Bb[it & 1];
#pragma unroll
        for (int ks = 0; ks < 4; ks++) {
            const int k8 = ks * 8 + kq;
            uint32_t af[MI][4], bf[NI][2];
#pragma unroll
            for (int mi = 0; mi < MI; mi++) {
                int r0 = wm + mi * 16 + gp;
                if constexpr (AT) {
                    af[mi][0] = __float_as_uint(As[r0 * 36 + k8]);
                    af[mi][1] = __float_as_uint(As[(r0 + 8) * 36 + k8]);
                    af[mi][2] = __float_as_uint(As[r0 * 36 + k8 + 4]);
                    af[mi][3] = __float_as_uint(As[(r0 + 8) * 36 + k8 + 4]);
                } else {
                    af[mi][0] = __float_as_uint(As[k8 * SA + r0]);
                    af[mi][1] = __float_as_uint(As[k8 * SA + r0 + 8]);
                    af[mi][2] = __float_as_uint(As[(k8 + 4) * SA + r0]);
                    af[mi][3] = __float_as_uint(As[(k8 + 4) * SA + r0 + 8]);
                }
            }
#pragma unroll
            for (int ni = 0; ni < NI; ni++) {
                int c0 = wn + ni * 8 + gp;
                if constexpr (BT) {
                    bf[ni][0] = __float_as_uint(Bs[c0 * 36 + k8]);
                    bf[ni][1] = __float_as_uint(Bs[c0 * 36 + k8 + 4]);
                } else {
                    bf[ni][0] = __float_as_uint(Bs[k8 * SB + c0]);
                    bf[ni][1] = __float_as_uint(Bs[(k8 + 4) * SB + c0]);
                }
            }
#pragma unroll
            for (int mi = 0; mi < MI; mi++)
#pragma unroll
                for (int ni = 0; ni < NI; ni++)
                    mma8(acc[mi][ni], af[mi], bf[ni]);
        }
        __syncthreads();
    }

    // epilogue
    float gs = 0.f;
#pragma unroll
    for (int mi = 0; mi < MI; mi++) {
#pragma unroll
        for (int ni = 0; ni < NI; ni++) {
            int r0 = bm + wm + mi * 16 + gp;
            int c = bn + wn + ni * 8 + kq * 2;
            size_t o0 = (size_t)r0 * N + c;
            size_t o1 = (size_t)(r0 + 8) * N + c;
            float2 v0 = make_float2(acc[mi][ni][0], acc[mi][ni][1]);
            float2 v1 = make_float2(acc[mi][ni][2], acc[mi][ni][3]);
            if (epi == EPI_SILU) {
                v0.x = silu_f(v0.x); v0.y = silu_f(v0.y);
                v1.x = silu_f(v1.x); v1.y = silu_f(v1.y);
            } else if (epi == EPI_SILU_AUX) {
                *(float2*)(aux + o0) = v0;
                *(float2*)(aux + o1) = v1;
                v0.x = silu_f(v0.x); v0.y = silu_f(v0.y);
                v1.x = silu_f(v1.x); v1.y = silu_f(v1.y);
            } else if (epi == EPI_DSILU) {
                float2 z0 = *(const float2*)(aux + o0);
                float2 z1 = *(const float2*)(aux + o1);
                v0.x *= dsilu_f(z0.x); v0.y *= dsilu_f(z0.y);
                v1.x *= dsilu_f(z1.x); v1.y *= dsilu_f(z1.y);
            } else if (epi >= EPI_GRAD) {
                gs += v0.x * v0.x + v0.y * v0.y + v1.x * v1.x + v1.y * v1.y;
            }
            *(float2*)(C + o0) = v0;
            *(float2*)(C + o1) = v1;
        }
    }
    if (epi >= EPI_GRAD) {
        gs = block_sum(gs);
        if (t == 0) atomicAdd(gn, gs);
        if (epi == EPI_GRAD_LN && bx == 0 && by == 0) {
            float s = 0.f;
            for (int i = t; i < HH; i += NT) { float d = aux[i]; s += d * d; }
            s = block_sum(s);
            if (t == 0) atomicAdd(gn, s);
        }
    }
}

template<int BM, int BN, int WM, int WN, int NWARP, bool AT, bool BT>
__global__ __launch_bounds__(NWARP * 32) void gemm_tc(
    const float* __restrict__ A, const float* __restrict__ B,
    float* __restrict__ C, float* __restrict__ aux, float* __restrict__ gn,
    int M, int N, int K, int lda, int ldb, int epi)
{
    extern __shared__ float sm[];
    gemm_body<BM, BN, WM, WN, NWARP, AT, BT>(sm, A, B, C, aux, gn, M, N, K, lda, ldb,
                                             epi, blockIdx.x, blockIdx.y);
}

// z split-K=2: zp[s][NN,II] = kc[:, s*512:+512] @ w0[:, s*512:+512]^T
__global__ __launch_bounds__(128) void gemm_z_sk(
    const float* __restrict__ kc, const float* __restrict__ w0, float* __restrict__ zp)
{
    extern __shared__ float sm[];
    int s = blockIdx.z;
    gemm_body<64, 128, 32, 64, 4, true, true>(
        sm, kc + s * (HH / 2), w0 + s * (HH / 2), zp + (size_t)s * NN * II,
        nullptr, nullptr, NN, II, HH / 2, HH, HH, EPI_NONE, blockIdx.x, blockIdx.y);
}

// y split-K=4: yp[s][NN,HH] = h[:, s*512:+512] @ w1[:, s*512:+512]^T
__global__ __launch_bounds__(128) void gemm_y_sk(
    const float* __restrict__ h, const float* __restrict__ w1, float* __restrict__ yp)
{
    extern __shared__ float sm[];
    int s = blockIdx.z;
    gemm_body<64, 128, 32, 64, 4, true, true>(
        sm, h + s * (II / 4), w1 + s * (II / 4), yp + (size_t)s * NN * HH,
        nullptr, nullptr, NN, HH, II / 4, II, II, EPI_NONE, blockIdx.x, blockIdx.y);
}

// fused: z∈{0,1}: dzp[z] = dy @ w1[z*512:+512,:]  (split-K partials)
//        z==2   : dw1 = dy^T @ h + grad sumsq
__global__ __launch_bounds__(128) void fused_dz_dw1(
    const float* __restrict__ dy, const float* __restrict__ w1,
    float* __restrict__ dzp,
    const float* __restrict__ h, float* __restrict__ dw1, float* __restrict__ gn)
{
    extern __shared__ float sm[];
    int s = blockIdx.z;
    if (s < 2)
        gemm_body<64, 128, 32, 64, 4, true, false>(
            sm, dy + s * (HH / 2), w1 + (size_t)s * (HH / 2) * II,
            dzp + (size_t)s * NN * II, nullptr, nullptr,
            NN, II, HH / 2, HH, II, EPI_NONE, blockIdx.x, blockIdx.y);
    else
        gemm_body<128, 128, 64, 64, 4, false, false>(
            sm, dy, h, dw1, nullptr, gn, HH, II, NN, HH, II, EPI_GRAD,
            blockIdx.x, blockIdx.y);
}

// ---------------- combine kernels ----------------
__global__ __launch_bounds__(256) void combine_z() {
    int i = blockIdx.x * 256 + threadIdx.x;   // over NN*II/4 float4s
    float4 a = ((const float4*)g_zp)[i];
    float4 b = ((const float4*)(g_zp + NN * II))[i];
    float4 zz;
    zz.x = a.x + b.x; zz.y = a.y + b.y; zz.z = a.z + b.z; zz.w = a.w + b.w;
    ((float4*)g_z)[i] = zz;
    float4 hh;
    hh.x = silu_f(zz.x); hh.y = silu_f(zz.y); hh.z = silu_f(zz.z); hh.w = silu_f(zz.w);
    ((float4*)g_h)[i] = hh;
}

__global__ __launch_bounds__(256) void combine_dz() {
    int i = blockIdx.x * 256 + threadIdx.x;
    float4 a = ((const float4*)g_dzp)[i];
    float4 b = ((const float4*)(g_dzp + NN * II))[i];
    float4 zz = ((const float4*)g_z)[i];
    float4 d;
    d.x = (a.x + b.x) * dsilu_f(zz.x);
    d.y = (a.y + b.y) * dsilu_f(zz.y);
    d.z = (a.z + b.z) * dsilu_f(zz.z);
    d.w = (a.w + b.w) * dsilu_f(zz.w);
    ((float4*)g_dz)[i] = d;
}

// ---------------- elementwise / reduction kernels ----------------
__global__ __launch_bounds__(256) void init_mem(
    const float* __restrict__ w0, const float* __restrict__ w1, const float* __restrict__ ln)
{
    int n = II * HH;
    for (int i = blockIdx.x * blockDim.x + threadIdx.x; i < n; i += gridDim.x * blockDim.x) {
        g_w0[i] = w0[i]; g_s0[i] = 0.f;
        g_w1[i] = w1[i]; g_s1[i] = 0.f;
        if (i < HH) { g_ln[i] = ln[i]; g_sln[i] = 0.f; }
        if (i < NCH * HH) g_dlnA[i] = 0.f;
        if (i < NCH) g_gnormA[i] = 0.f;
    }
}

__global__ __launch_bounds__(256) void rmsnorm_rows(float* __restrict__ buf, const float* __restrict__ w) {
    int r = blockIdx.x;
    int t = threadIdx.x;
    float4* row = (float4*)(buf + (size_t)r * HH);
    float4 v = row[t];
    float ss = v.x * v.x + v.y * v.y + v.z * v.z + v.w * v.w;
    ss = block_sum(ss);
    float rs = rsqrtf(ss / HH + 1e-6f);
    float4 wv = ((const float4*)w)[t];
    v.x *= rs * wv.x; v.y *= rs * wv.y; v.z *= rs * wv.z; v.w *= rs * wv.w;
    row[t] = v;
}

__global__ __launch_bounds__(256) void gather_all() {
    const int H4 = HH / 4;
    const int per = NN * H4;
    int ntot = NCH * per;
    for (int i = blockIdx.x * blockDim.x + threadIdx.x; i < ntot; i += gridDim.x * blockDim.x) {
        int c = i / per, rem = i - c * per;
        int m = rem / H4, q = rem - m * H4;
        int src = ((m >> 6) * SS + c * CC + (m & 63)) * H4 + q;
        ((float4*)g_kall)[i] = ((const float4*)g_k)[src];
        ((float4*)g_vall)[i] = ((const float4*)g_v)[src];
    }
}

__global__ __launch_bounds__(256) void coeff_dot(
    const float* __restrict__ x, const float* __restrict__ aw,
    const float* __restrict__ tw, const float* __restrict__ ew)
{
    int bc = blockIdx.x;
    int b = bc >> 5, nc = bc & 31;
    const float4* xf = (const float4*)(x + (size_t)(b * SS + nc * CC) * HH);
    const float4* a4 = (const float4*)aw;
    const float4* t4 = (const float4*)tw;
    const float4* e4 = (const float4*)ew;
    const int L4 = CC * HH / 4;
    float sa = 0.f, st = 0.f, se = 0.f;
    for (int i = threadIdx.x; i < L4; i += blockDim.x) {
        float4 xv = xf[i];
        float4 av = a4[i]; sa += xv.x * av.x + xv.y * av.y + xv.z * av.z + xv.w * av.w;
        float4 tv = t4[i]; st += xv.x * tv.x + xv.y * tv.y + xv.z * tv.z + xv.w * tv.w;
        float4 ev = e4[i]; se += xv.x * ev.x + xv.y * ev.y + xv.z * ev.z + xv.w * ev.w;
    }
    sa = block_sum(sa);
    st = block_sum(st);
    se = block_sum(se);
    if (threadIdx.x == 0) { g_dotA[bc] = sa; g_dotT[bc] = st; g_dotE[bc] = se; }
}

__global__ void coeff_finalize() {
    int t = threadIdx.x;
    if (t < BB * NCH) g_theta[t] = sigm(g_dotT[t]) * 0.01f;
    if (t < NCH) {
        float sa = 0.f, se = 0.f;
        for (int b = 0; b < BB; b++) { sa += g_dotA[b * NCH + t]; se += g_dotE[b * NCH + t]; }
        float al = sigm(sa / (float)BB);
        g_beta[t] = 1.f - al;
        g_eta[t] = sigm(se / (float)BB);
    }
}

// backward through rmsnorm + residual + weighted MSE; combines 4 split-K y parts
__global__ __launch_bounds__(256) void chunk_bwd_y(int c) {
    int r = blockIdx.x;
    int t = threadIdx.x;
    int b = r >> 6;
    const float* kc = g_kall + (size_t)c * NN * HH;
    const float* vc = g_vall + (size_t)c * NN * HH;
    float4 y0 = ((const float4*)(g_y + (size_t)r * HH))[t];
    float4 y1 = ((const float4*)(g_y + (size_t)(NN + r) * HH))[t];
    float4 y2 = ((const float4*)(g_y + (size_t)(2 * NN + r) * HH))[t];
    float4 y3 = ((const float4*)(g_y + (size_t)(3 * NN + r) * HH))[t];
    float4 y4;
    y4.x = (y0.x + y1.x) + (y2.x + y3.x);
    y4.y = (y0.y + y1.y) + (y2.y + y3.y);
    y4.z = (y0.z + y1.z) + (y2.z + y3.z);
    y4.w = (y0.w + y1.w) + (y2.w + y3.w);
    float ss = y4.x * y4.x + y4.y * y4.y + y4.z * y4.z + y4.w * y4.w;
    ss = block_sum(ss);
    float rs = rsqrtf(ss / HH + 1e-6f);
    float th = g_theta[b * NCH + c];
    float scale = 2.f * th / ((float)NN * (float)HH);
    float4 k4 = ((const float4*)(kc + (size_t)r * HH))[t];
    float4 v4 = ((const float4*)(vc + (size_t)r * HH))[t];
    float4 l4 = ((const float4*)g_ln)[t];
    float4 gg;
    gg.x = scale * (k4.x + y4.x * rs * l4.x - v4.x);
    gg.y = scale * (k4.y + y4.y * rs * l4.y - v4.y);
    gg.z = scale * (k4.z + y4.z * rs * l4.z - v4.z);
    gg.w = scale * (k4.w + y4.w * rs * l4.w - v4.w);
    float sv = gg.x * l4.x * y4.x + gg.y * l4.y * y4.y + gg.z * l4.z * y4.z + gg.w * l4.w * y4.w;
    sv = block_sum(sv);
    float c3 = rs * rs * rs * sv / (float)HH;
    float4 dy;
    dy.x = rs * gg.x * l4.x - c3 * y4.x;
    dy.y = rs * gg.y * l4.y - c3 * y4.y;
    dy.z = rs * gg.z * l4.z - c3 * y4.z;
    dy.w = rs * gg.w * l4.w - c3 * y4.w;
    ((float4*)(g_dy + (size_t)r * HH))[t] = dy;
    float* dln = g_dlnA + c * HH;
    atomicAdd(&dln[t * 4 + 0], gg.x * y4.x * rs);
    atomicAdd(&dln[t * 4 + 1], gg.y * y4.y * rs);
    atomicAdd(&dln[t * 4 + 2], gg.z * y4.z * rs);
    atomicAdd(&dln[t * 4 + 3], gg.w * y4.w * rs);
}

__global__ __launch_bounds__(256) void update_params(int c) {
    float total = sqrtf(g_gnormA[c]);
    float clip = fminf(1.0f / (total + 1e-6f), 1.0f);
    float eta = g_eta[c], beta = g_beta[c];
    const float* dln = g_dlnA + c * HH;
    const int n0 = II * HH, n1 = 2 * II * HH, nt = 2 * II * HH + HH;
    for (int i = blockIdx.x * blockDim.x + threadIdx.x; i < nt; i += gridDim.x * blockDim.x) {
        if (i < n0) {
            float ns = eta * g_s0[i] - g_dw0[i] * clip;
            g_s0[i] = ns;
            g_w0[i] = beta * g_w0[i] + ns;
        } else if (i < n1) {
            int j = i - n0;
            float ns = eta * g_s1[j] - g_dw1[j] * clip;
            g_s1[j] = ns;
            g_w1[j] = beta * g_w1[j] + ns;
        } else {
            int j = i - n1;
            float ns = eta * g_sln[j] - dln[j] * clip;
            g_sln[j] = ns;
            g_ln[j] = beta * g_ln[j] + ns;
        }
    }
}

__global__ __launch_bounds__(256) void final_out(float* __restrict__ out) {
    int r = blockIdx.x, t = threadIdx.x;
    float4 y4 = ((const float4*)(g_y2 + (size_t)r * HH))[t];
    float ss = y4.x * y4.x + y4.y * y4.y + y4.z * y4.z + y4.w * y4.w;
    ss = block_sum(ss);
    float rs = rsqrtf(ss / HH + 1e-6f);
    float4 q4 = ((const float4*)(g_q + (size_t)r * HH))[t];
    float4 l4 = ((const float4*)g_ln)[t];
    float4 o;
    o.x = q4.x + y4.x * rs * l4.x;
    o.y = q4.y + y4.y * rs * l4.y;
    o.z = q4.z + y4.z * rs * l4.z;
    o.w = q4.w + y4.w * rs * l4.w;
    ((float4*)(out + (size_t)r * HH))[t] = o;
}

// ---------------- host launcher ----------------
extern "C" void kernel_launch(void* const* d_in, const int* in_sizes, int n_in,
                              void* d_out, int out_size) {
    const float* x   = (const float*)d_in[0];
    const float* wq  = (const float*)d_in[1];
    const float* wk  = (const float*)d_in[2];
    const float* wv  = (const float*)d_in[3];
    const float* qn  = (const float*)d_in[4];
    const float* kn  = (const float*)d_in[5];
    const float* aw  = (const float*)d_in[6];
    const float* tw  = (const float*)d_in[7];
    const float* ew  = (const float*)d_in[8];
    const float* mw0 = (const float*)d_in[9];
    const float* mw1 = (const float*)d_in[10];
    const float* mln = (const float*)d_in[11];
    float* out = (float*)d_out;

    float *k_, *v_, *q_, *w0_, *w1_, *kall_, *zp_, *h_, *y_, *dy_, *dz_, *dzp_;
    float *dw0_, *dw1_, *dlnA_, *gnA_, *h2_, *y2_;
    cudaGetSymbolAddress((void**)&k_,    g_k);
    cudaGetSymbolAddress((void**)&v_,    g_v);
    cudaGetSymbolAddress((void**)&q_,    g_q);
    cudaGetSymbolAddress((void**)&w0_,   g_w0);
    cudaGetSymbolAddress((void**)&w1_,   g_w1);
    cudaGetSymbolAddress((void**)&kall_, g_kall);
    cudaGetSymbolAddress((void**)&zp_,   g_zp);
    cudaGetSymbolAddress((void**)&h_,    g_h);
    cudaGetSymbolAddress((void**)&y_,    g_y);
    cudaGetSymbolAddress((void**)&dy_,   g_dy);
    cudaGetSymbolAddress((void**)&dz_,   g_dz);
    cudaGetSymbolAddress((void**)&dzp_,  g_dzp);
    cudaGetSymbolAddress((void**)&dw0_,  g_dw0);
    cudaGetSymbolAddress((void**)&dw1_,  g_dw1);
    cudaGetSymbolAddress((void**)&dlnA_, g_dlnA);
    cudaGetSymbolAddress((void**)&gnA_,  g_gnormA);
    cudaGetSymbolAddress((void**)&h2_,   g_h2);
    cudaGetSymbolAddress((void**)&y2_,   g_y2);

    // 64x32 warp tiles everywhere for 3 blocks/SM occupancy
    auto G1 = gemm_tc<128,64,64,32,4,true,true>;    // big parallel NT
    auto Gw = gemm_tc<128,128,64,64,4,false,false>; // TN dw0
    const int S1 = 2 * (128*36 + 64*36) * 4;        // 55296
    const int Sz = 2 * (64*36 + 128*36) * 4;        // 55296
    const int Sy = Sz;
    const int Sw = 2 * (32*136 + 32*136) * 4;       // 69632
    const int Sf = Sw;
    static int attr_done = 0;
    if (!attr_done) {
        cudaFuncSetAttribute(G1, cudaFuncAttributeMaxDynamicSharedMemorySize, S1);
        cudaFuncSetAttribute(gemm_z_sk, cudaFuncAttributeMaxDynamicSharedMemorySize, Sz);
        cudaFuncSetAttribute(gemm_y_sk, cudaFuncAttributeMaxDynamicSharedMemorySize, Sy);
        cudaFuncSetAttribute(Gw, cudaFuncAttributeMaxDynamicSharedMemorySize, Sw);
        cudaFuncSetAttribute(fused_dz_dw1, cudaFuncAttributeMaxDynamicSharedMemorySize, Sf);
        attr_done = 1;
    }

    // ---- init memory params ----
    init_mem<<<2048, 256>>>(mw0, mw1, mln);

    // ---- precompute k, v, q ----
    dim3 gKVQ(HH / 64, NROWS / 128);
    G1<<<gKVQ, 128, S1>>>(x, wk, k_, nullptr, nullptr, NROWS, HH, HH, HH, HH, EPI_SILU);
    rmsnorm_rows<<<NROWS, 256>>>(k_, kn);
    G1<<<gKVQ, 128, S1>>>(x, wv, v_, nullptr, nullptr, NROWS, HH, HH, HH, HH, EPI_SILU);
    G1<<<gKVQ, 128, S1>>>(x, wq, q_, nullptr, nullptr, NROWS, HH, HH, HH, HH, EPI_SILU);
    rmsnorm_rows<<<NROWS, 256>>>(q_, qn);
    gather_all<<<2048, 256>>>();

    // ---- adaptive coefficients ----
    coeff_dot<<<BB * NCH, 256>>>(x, aw, tw, ew);
    coeff_finalize<<<1, 256>>>();

    // ---- sequential scan over chunks ----
    for (int c = 0; c < NCH; c++) {
        const float* kc = kall_ + (size_t)c * NN * HH;
        // z partials (split-K=2, 256 blocks)
        gemm_z_sk<<<dim3(II / 128, NN / 64, 2), 128, Sz>>>(kc, w0_, zp_);
        // z = z0+z1, h = silu(z)
        combine_z<<<NN * II / 1024, 256>>>();
        // y partials (split-K=4, 256 blocks)
        gemm_y_sk<<<dim3(HH / 128, NN / 64, 4), 128, Sy>>>(h_, w1_, y_);
        // backward through residual + rmsnorm + MSE (sums 4 y partials)
        chunk_bwd_y<<<NN, 256>>>(c);
        // dz partials (split-K=2) || dw1 (+grad sumsq) — one launch, 384 blocks
        fused_dz_dw1<<<dim3(16, 8, 3), 128, Sf>>>(dy_, w1_, dzp_, h_, dw1_, gnA_ + c);
        // dz = (dz0+dz1)*dsilu(z)
        combine_dz<<<NN * II / 1024, 256>>>();
        // dw0 = dz^T @ kc (+grad sumsq + dln^2)
        Gw<<<dim3(HH / 128, II / 128), 128, Sw>>>(dz_, kc, dw0_, dlnA_ + c * HH, gnA_ + c, II, HH, NN, II, HH, EPI_GRAD_LN);
        // clipped EMA update
        update_params<<<1024, 256>>>(c);
    }

    // ---- retrieval with final memory ----
    G1<<<dim3(II / 64, NROWS / 128), 128, S1>>>(q_, w0_, h2_, nullptr, nullptr, NROWS, II, HH, HH, HH, EPI_SILU);
    G1<<<dim3(HH / 64, NROWS / 128), 128, S1>>>(h2_, w1_, y2_, nullptr, nullptr, NROWS, HH, II, II, II, EPI_NONE);
    final_out<<<NROWS, 256>>>(out);
}